// round 5
// baseline (speedup 1.0000x reference)
#include <cuda_runtime.h>

#define BB   8
#define CC   64
#define HH   128
#define WW   128
#define OO   64
#define OOFF 18
#define KK   9
#define HWSZ (HH*WW)

// ---------------- scratch (no allocations allowed) ----------------
__device__ __align__(16) float g_xt[BB*HWSZ*CC];       // x in NHWC, 33.5MB
__device__ __align__(16) float g_off[BB*HWSZ*OOFF];    // offsets NHWC, 9.4MB
__device__ __align__(16) float g_wt[KK*CC*OO];         // main weights [k][c][o]
__device__ __align__(16) float g_wtoff[KK*CC*OOFF];    // offset weights [k][c][o]

// ---------------- kernel 1: NCHW -> NHWC transpose ----------------
__global__ void k_transpose(const float* __restrict__ x) {
    __shared__ float tile[32][33];
    int b   = blockIdx.z;
    int hw0 = blockIdx.x * 32;
    int c0  = blockIdx.y * 32;
    int tx = threadIdx.x, ty = threadIdx.y;
    const float* xp = x + (size_t)b * CC * HWSZ;
#pragma unroll
    for (int i = 0; i < 32; i += 8)
        tile[ty + i][tx] = xp[(c0 + ty + i) * HWSZ + hw0 + tx];
    __syncthreads();
    float* op = g_xt + (size_t)b * HWSZ * CC;
#pragma unroll
    for (int i = 0; i < 32; i += 8)
        op[(hw0 + ty + i) * CC + c0 + tx] = tile[tx][ty + i];
}

// ---------------- kernel 2: weight transposes ----------------
__global__ void k_wprep(const float* __restrict__ w, const float* __restrict__ woff) {
    int i = blockIdx.x * 256 + threadIdx.x;
    if (i < KK * CC * OO) {
        int k = i / (CC * OO);
        int r = i % (CC * OO);
        int c = r / OO;
        int o = r % OO;
        g_wt[i] = w[(o * CC + c) * KK + k];
    }
    if (i < KK * CC * OOFF) {
        int k = i / (CC * OOFF);
        int r = i % (CC * OOFF);
        int c = r / OOFF;
        int o = r % OOFF;
        g_wtoff[i] = woff[(o * CC + c) * KK + k];
    }
}

// ---------------- kernel 3: offset conv (Cin=64 -> 18, 3x3, pad 1) ----------------
// 1 thread per output pixel, 18 register accumulators, weights broadcast from smem.
__global__ __launch_bounds__(256) void k_offconv(const float* __restrict__ boff) {
    __shared__ __align__(16) float ws[KK * CC * OOFF];   // 41.5 KB
    int tid = threadIdx.x;
    for (int i = tid * 4; i < KK * CC * OOFF; i += 1024)
        *(float4*)&ws[i] = *(const float4*)&g_wtoff[i];
    __syncthreads();

    int b  = blockIdx.y;
    int ho = blockIdx.x * 2 + (tid >> 7);
    int wo = tid & 127;

    float acc[OOFF];
#pragma unroll
    for (int o = 0; o < OOFF; o++) acc[o] = 0.f;

#pragma unroll 1
    for (int k = 0; k < KK; k++) {
        int ki = k / 3, kj = k % 3;
        int y = ho + ki - 1, x = wo + kj - 1;
        float m = (y >= 0 && y < HH && x >= 0 && x < WW) ? 1.f : 0.f;
        int yc = min(max(y, 0), HH - 1);
        int xc = min(max(x, 0), WW - 1);
        const float* px = g_xt + (b * HWSZ + yc * WW + xc) * CC;
        const float* wk = &ws[k * CC * OOFF];
#pragma unroll 4
        for (int c = 0; c < CC; c += 4) {
            float4 v = *(const float4*)(px + c);
            float vv0 = v.x * m, vv1 = v.y * m, vv2 = v.z * m, vv3 = v.w * m;
#pragma unroll
            for (int cc = 0; cc < 4; cc++) {
                float vc = (cc == 0) ? vv0 : (cc == 1) ? vv1 : (cc == 2) ? vv2 : vv3;
                const float* wr = wk + (c + cc) * OOFF;
#pragma unroll
                for (int o2 = 0; o2 < 9; o2++) {
                    float2 wv = *(const float2*)(wr + o2 * 2);
                    acc[o2 * 2]     += vc * wv.x;
                    acc[o2 * 2 + 1] += vc * wv.y;
                }
            }
        }
    }
    float* op = g_off + (b * HWSZ + ho * WW + wo) * OOFF;
#pragma unroll
    for (int o = 0; o < OOFF; o++) op[o] = acc[o] + boff[o];
}

// ---------------- kernel 4: deformable conv ----------------
// Block: 64 pixels (half row) x 64 outputs. Per tap k:
//   params (64 thr) -> bilinear sample into smem (256 thr) -> register-tiled GEMM.
#define SSTR 68   // padded pixel stride in smem (17 float4 -> keeps 16B align)
__global__ __launch_bounds__(256) void k_deform(const float* __restrict__ bias,
                                                float* __restrict__ out) {
    __shared__ __align__(16) float s_w[CC * OO];          // 16 KB  [j][o]
    __shared__ __align__(16) float s_samp[64 * SSTR];     // 17.4 KB [pix][ch] (reused as out stage)
    __shared__ int   s_iy0[64], s_iy1[64], s_ix0[64], s_ix1[64];
    __shared__ float s_w00[64], s_w01[64], s_w10[64], s_w11[64];

    int tid = threadIdx.x;
    int b   = blockIdx.z;
    int ho  = blockIdx.y;
    int wo0 = blockIdx.x * 64;

    int lane  = tid & 31;
    int wid   = tid >> 5;
    int pbase = wid * 8 + (lane >> 4) * 4;   // this lane's 4 pixels
    int o0    = (lane & 15) * 4;             // this lane's 4 output channels

    float acc[4][4];
#pragma unroll
    for (int i = 0; i < 4; i++)
#pragma unroll
        for (int j = 0; j < 4; j++) acc[i][j] = 0.f;

    int sp = tid >> 2;            // sampling: pixel
    int cq = (tid & 3) << 4;      // sampling: channel-quad base (16 ch)

#pragma unroll 1
    for (int k = 0; k < KK; k++) {
        __syncthreads();   // previous tap's GEMM done with s_w / s_samp

        // stage this tap's weights [64c][64o]
#pragma unroll
        for (int i = 0; i < 4; i++) {
            int idx = tid * 4 + i * 1024;
            *(float4*)&s_w[idx] = *(const float4*)&g_wt[k * CC * OO + idx];
        }

        // per-pixel bilinear params
        if (tid < 64) {
            int p = tid, wo = wo0 + p;
            const float* offp = g_off + (b * HWSZ + ho * WW + wo) * OOFF + 2 * k;
            float dy = offp[0], dx = offp[1];
            int ki = k / 3, kj = k % 3;
            float py = (float)(ho - 1 + ki) + dy;
            float px = (float)(wo - 1 + kj) + dx;
            float fy = floorf(py), fx = floorf(px);
            float wy = py - fy, wx = px - fx;
            int iy = (int)fy, ix = (int)fx;
            float vy0 = (iy >= 0 && iy < HH) ? 1.f : 0.f;
            float vy1 = (iy + 1 >= 0 && iy + 1 < HH) ? 1.f : 0.f;
            float vx0 = (ix >= 0 && ix < WW) ? 1.f : 0.f;
            float vx1 = (ix + 1 >= 0 && ix + 1 < WW) ? 1.f : 0.f;
            s_w00[p] = (1.f - wy) * (1.f - wx) * vy0 * vx0;
            s_w01[p] = (1.f - wy) * wx         * vy0 * vx1;
            s_w10[p] = wy         * (1.f - wx) * vy1 * vx0;
            s_w11[p] = wy         * wx         * vy1 * vx1;
            s_iy0[p] = min(max(iy, 0), HH - 1);
            s_iy1[p] = min(max(iy + 1, 0), HH - 1);
            s_ix0[p] = min(max(ix, 0), WW - 1);
            s_ix1[p] = min(max(ix + 1, 0), WW - 1);
        }
        __syncthreads();

        // bilinear sampling: thread -> (pixel sp, 16 channels at cq)
        {
            int iy0 = s_iy0[sp], iy1 = s_iy1[sp], ix0 = s_ix0[sp], ix1 = s_ix1[sp];
            float w00 = s_w00[sp], w01 = s_w01[sp], w10 = s_w10[sp], w11 = s_w11[sp];
            const float* xb  = g_xt + b * HWSZ * CC;
            const float* p00 = xb + (iy0 * WW + ix0) * CC + cq;
            const float* p01 = xb + (iy0 * WW + ix1) * CC + cq;
            const float* p10 = xb + (iy1 * WW + ix0) * CC + cq;
            const float* p11 = xb + (iy1 * WW + ix1) * CC + cq;
            float* dst = &s_samp[sp * SSTR + cq];
#pragma unroll
            for (int i = 0; i < 4; i++) {
                float4 a0 = *(const float4*)(p00 + i * 4);
                float4 a1 = *(const float4*)(p01 + i * 4);
                float4 a2 = *(const float4*)(p10 + i * 4);
                float4 a3 = *(const float4*)(p11 + i * 4);
                float4 r;
                r.x = a0.x * w00 + a1.x * w01 + a2.x * w10 + a3.x * w11;
                r.y = a0.y * w00 + a1.y * w01 + a2.y * w10 + a3.y * w11;
                r.z = a0.z * w00 + a1.z * w01 + a2.z * w10 + a3.z * w11;
                r.w = a0.w * w00 + a1.w * w01 + a2.w * w10 + a3.w * w11;
                *(float4*)(dst + i * 4) = r;
            }
        }
        __syncthreads();

        // GEMM: 4 pixels x 4 outputs per lane, accumulate over 64 channels
        const float* sr0 = &s_samp[(pbase + 0) * SSTR];
        const float* sr1 = &s_samp[(pbase + 1) * SSTR];
        const float* sr2 = &s_samp[(pbase + 2) * SSTR];
        const float* sr3 = &s_samp[(pbase + 3) * SSTR];
#pragma unroll
        for (int j = 0; j < CC; j++) {
            float4 wv = *(const float4*)&s_w[j * OO + o0];
            float s0 = sr0[j], s1 = sr1[j], s2 = sr2[j], s3 = sr3[j];
            acc[0][0] += s0 * wv.x; acc[0][1] += s0 * wv.y; acc[0][2] += s0 * wv.z; acc[0][3] += s0 * wv.w;
            acc[1][0] += s1 * wv.x; acc[1][1] += s1 * wv.y; acc[1][2] += s1 * wv.z; acc[1][3] += s1 * wv.w;
            acc[2][0] += s2 * wv.x; acc[2][1] += s2 * wv.y; acc[2][2] += s2 * wv.z; acc[2][3] += s2 * wv.w;
            acc[3][0] += s3 * wv.x; acc[3][1] += s3 * wv.y; acc[3][2] += s3 * wv.z; acc[3][3] += s3 * wv.w;
        }
    }

    // stage to smem as [o][p] for coalesced NCHW stores
    __syncthreads();
    float* s_out = s_samp;   // 4096 floats <= 4352
#pragma unroll
    for (int pi = 0; pi < 4; pi++)
#pragma unroll
        for (int oi = 0; oi < 4; oi++)
            s_out[(o0 + oi) * 64 + (pbase + pi)] = acc[pi][oi];
    __syncthreads();

    float* ob = out + (b * OO) * HWSZ + ho * WW + wo0;
    for (int i = tid; i < 64 * 64; i += 256) {
        int o = i >> 6, p = i & 63;
        ob[o * HWSZ + p] = s_out[i] + bias[o];
    }
}

// ---------------- launch ----------------
extern "C" void kernel_launch(void* const* d_in, const int* in_sizes, int n_in,
                              void* d_out, int out_size) {
    const float* x     = (const float*)d_in[0];
    const float* w_off = (const float*)d_in[1];
    const float* b_off = (const float*)d_in[2];
    const float* w     = (const float*)d_in[3];
    const float* bias  = (const float*)d_in[4];
    float* out = (float*)d_out;

    (void)in_sizes; (void)n_in; (void)out_size;

    dim3 tpb(32, 8);
    k_transpose<<<dim3(HWSZ / 32, CC / 32, BB), tpb>>>(x);
    k_wprep<<<(KK * CC * OO + 255) / 256, 256>>>(w, w_off);
    k_offconv<<<dim3(HH / 2, BB), 256>>>(b_off);
    k_deform<<<dim3(WW / 64, HH, BB), 256>>>(bias, out);
}

// round 6
// speedup vs baseline: 1.0690x; 1.0690x over previous
#include <cuda_runtime.h>
#include <cstdint>

#define BB   8
#define CC   64
#define HH   128
#define WW   128
#define OO   64
#define OOFF 18
#define KK   9
#define HWSZ (HH*WW)

#define PIX  128   // pixels per block in k_deform (one full row)
#define SSTR 68    // sample smem pixel stride (floats) -> conflict-free A frags
#define WSTR 72    // weight smem row stride (floats)  -> conflict-free B frags

// ---------------- scratch (no allocations allowed) ----------------
__device__ __align__(16) float g_xt[BB*HWSZ*CC];       // x in NHWC
__device__ __align__(16) float g_off[BB*HWSZ*OOFF];    // offsets NHWC
__device__ __align__(16) float g_wt[KK*CC*OO];         // main weights [k][c][o], tf32-rounded
__device__ __align__(16) float g_wtoff[KK*CC*OOFF];    // offset weights [k][c][o], fp32

__device__ __forceinline__ uint32_t f2tf32(float f) {
    uint32_t r;
    asm("cvt.rna.tf32.f32 %0, %1;" : "=r"(r) : "f"(f));
    return r;
}

#define MMA_TF32(d, a, b)                                                     \
    asm volatile("mma.sync.aligned.m16n8k8.row.col.f32.tf32.tf32.f32 "        \
                 "{%0,%1,%2,%3}, {%4,%5,%6,%7}, {%8,%9}, {%0,%1,%2,%3};"      \
                 : "+f"(d[0]), "+f"(d[1]), "+f"(d[2]), "+f"(d[3])             \
                 : "r"(a[0]), "r"(a[1]), "r"(a[2]), "r"(a[3]),                \
                   "r"(b[0]), "r"(b[1]))

// ---------------- kernel 1: NCHW -> NHWC transpose ----------------
__global__ void k_transpose(const float* __restrict__ x) {
    __shared__ float tile[32][33];
    int b   = blockIdx.z;
    int hw0 = blockIdx.x * 32;
    int c0  = blockIdx.y * 32;
    int tx = threadIdx.x, ty = threadIdx.y;
    const float* xp = x + (size_t)b * CC * HWSZ;
#pragma unroll
    for (int i = 0; i < 32; i += 8)
        tile[ty + i][tx] = xp[(c0 + ty + i) * HWSZ + hw0 + tx];
    __syncthreads();
    float* op = g_xt + (size_t)b * HWSZ * CC;
#pragma unroll
    for (int i = 0; i < 32; i += 8)
        op[(hw0 + ty + i) * CC + c0 + tx] = tile[tx][ty + i];
}

// ---------------- kernel 2: weight transposes ----------------
__global__ void k_wprep(const float* __restrict__ w, const float* __restrict__ woff) {
    int i = blockIdx.x * 256 + threadIdx.x;
    if (i < KK * CC * OO) {
        int k = i / (CC * OO);
        int r = i % (CC * OO);
        int c = r / OO;
        int o = r % OO;
        // round main weights to tf32 once (rna); stored bit-pattern is valid fp32
        g_wt[i] = __uint_as_float(f2tf32(w[(o * CC + c) * KK + k]));
    }
    if (i < KK * CC * OOFF) {
        int k = i / (CC * OOFF);
        int r = i % (CC * OOFF);
        int c = r / OOFF;
        int o = r % OOFF;
        g_wtoff[i] = woff[(o * CC + c) * KK + k];
    }
}

// ---------------- kernel 3: offset conv (Cin=64 -> 18, 3x3, pad 1), fp32 ----------------
__global__ __launch_bounds__(256) void k_offconv(const float* __restrict__ boff) {
    __shared__ __align__(16) float ws[KK * CC * OOFF];
    int tid = threadIdx.x;
    for (int i = tid * 4; i < KK * CC * OOFF; i += 1024)
        *(float4*)&ws[i] = *(const float4*)&g_wtoff[i];
    __syncthreads();

    int b  = blockIdx.y;
    int ho = blockIdx.x * 2 + (tid >> 7);
    int wo = tid & 127;

    float acc[OOFF];
#pragma unroll
    for (int o = 0; o < OOFF; o++) acc[o] = 0.f;

#pragma unroll 1
    for (int k = 0; k < KK; k++) {
        int ki = k / 3, kj = k % 3;
        int y = ho + ki - 1, x = wo + kj - 1;
        float m = (y >= 0 && y < HH && x >= 0 && x < WW) ? 1.f : 0.f;
        int yc = min(max(y, 0), HH - 1);
        int xc = min(max(x, 0), WW - 1);
        const float* px = g_xt + (b * HWSZ + yc * WW + xc) * CC;
        const float* wk = &ws[k * CC * OOFF];
#pragma unroll 4
        for (int c = 0; c < CC; c += 4) {
            float4 v = *(const float4*)(px + c);
            float vv0 = v.x * m, vv1 = v.y * m, vv2 = v.z * m, vv3 = v.w * m;
#pragma unroll
            for (int cc = 0; cc < 4; cc++) {
                float vc = (cc == 0) ? vv0 : (cc == 1) ? vv1 : (cc == 2) ? vv2 : vv3;
                const float* wr = wk + (c + cc) * OOFF;
#pragma unroll
                for (int o2 = 0; o2 < 9; o2++) {
                    float2 wv = *(const float2*)(wr + o2 * 2);
                    acc[o2 * 2]     += vc * wv.x;
                    acc[o2 * 2 + 1] += vc * wv.y;
                }
            }
        }
    }
    float* op = g_off + (b * HWSZ + ho * WW + wo) * OOFF;
#pragma unroll
    for (int o = 0; o < OOFF; o++) op[o] = acc[o] + boff[o];
}

// ---------------- kernel 4: deformable conv, tf32 mma.sync ----------------
// Block = one row (128 pixels) x 64 outputs. Per tap:
//   stage weights + bilinear params -> sample into smem (tf32) -> warp-tiled MMA.
// Warp tile: 32 pixels x 32 outputs (2 m-frags x 4 n-tiles of m16n8k8).
__global__ __launch_bounds__(256) void k_deform(const float* __restrict__ bias,
                                                float* __restrict__ out) {
    extern __shared__ __align__(16) float smem[];
    float* s_w    = smem;                       // [CC][WSTR]   18432 B
    float* s_samp = smem + CC * WSTR;           // [PIX][SSTR]  34816 B (reused for out)
    float* s_w00  = s_samp + PIX * SSTR;        // 4 * PIX floats
    float* s_w01  = s_w00 + PIX;
    float* s_w10  = s_w01 + PIX;
    float* s_w11  = s_w10 + PIX;
    int*   s_iy0  = (int*)(s_w11 + PIX);        // 4 * PIX ints
    int*   s_iy1  = s_iy0 + PIX;
    int*   s_ix0  = s_iy1 + PIX;
    int*   s_ix1  = s_ix0 + PIX;

    int tid  = threadIdx.x;
    int b    = blockIdx.y;
    int ho   = blockIdx.x;
    int lane = tid & 31;
    int wid  = tid >> 5;

    int g  = lane >> 2;         // mma group id (0..7)
    int tg = lane & 3;          // thread-in-group (0..3)
    int p0 = (wid >> 1) * 32;   // warp pixel base (0,32,64,96)
    int n0 = (wid & 1) * 32;    // warp output base (0,32)

    float acc[2][4][4];
#pragma unroll
    for (int mf = 0; mf < 2; mf++)
#pragma unroll
        for (int nt = 0; nt < 4; nt++)
#pragma unroll
            for (int c = 0; c < 4; c++) acc[mf][nt][c] = 0.f;

    int sp  = tid >> 1;          // sampling pixel
    int ch0 = (tid & 1) * 32;    // sampling channel base (32 ch per thread)

#pragma unroll 1
    for (int k = 0; k < KK; k++) {
        __syncthreads();   // previous tap's GEMM done with s_w / s_samp

        // stage tap weights [64c][WSTR pad] as float4
        {
            const float4* src = (const float4*)&g_wt[k * CC * OO];
#pragma unroll
            for (int t = 0; t < 4; t++) {
                int idx = tid + t * 256;          // float4 index over 64x64
                int j = idx >> 4, o4 = (idx & 15) * 4;
                *(float4*)&s_w[j * WSTR + o4] = src[idx];
            }
        }

        // bilinear params for 128 pixels
        if (tid < PIX) {
            int p = tid;
            const float* offp = g_off + (b * HWSZ + ho * WW + p) * OOFF + 2 * k;
            float dy = offp[0], dx = offp[1];
            int ki = k / 3, kj = k % 3;
            float py = (float)(ho - 1 + ki) + dy;
            float px = (float)(p - 1 + kj) + dx;
            float fy = floorf(py), fx = floorf(px);
            float wy = py - fy, wx = px - fx;
            int iy = (int)fy, ix = (int)fx;
            float vy0 = (iy >= 0 && iy < HH) ? 1.f : 0.f;
            float vy1 = (iy + 1 >= 0 && iy + 1 < HH) ? 1.f : 0.f;
            float vx0 = (ix >= 0 && ix < WW) ? 1.f : 0.f;
            float vx1 = (ix + 1 >= 0 && ix + 1 < WW) ? 1.f : 0.f;
            s_w00[p] = (1.f - wy) * (1.f - wx) * vy0 * vx0;
            s_w01[p] = (1.f - wy) * wx         * vy0 * vx1;
            s_w10[p] = wy         * (1.f - wx) * vy1 * vx0;
            s_w11[p] = wy         * wx         * vy1 * vx1;
            s_iy0[p] = min(max(iy, 0), HH - 1);
            s_iy1[p] = min(max(iy + 1, 0), HH - 1);
            s_ix0[p] = min(max(ix, 0), WW - 1);
            s_ix1[p] = min(max(ix + 1, 0), WW - 1);
        }
        __syncthreads();

        // bilinear sampling -> s_samp (tf32-rounded), thread = (pixel, 32 channels)
        {
            int iy0 = s_iy0[sp], iy1 = s_iy1[sp], ix0 = s_ix0[sp], ix1 = s_ix1[sp];
            float w00 = s_w00[sp], w01 = s_w01[sp], w10 = s_w10[sp], w11 = s_w11[sp];
            const float* xb  = g_xt + b * HWSZ * CC;
            const float* p00 = xb + (iy0 * WW + ix0) * CC + ch0;
            const float* p01 = xb + (iy0 * WW + ix1) * CC + ch0;
            const float* p10 = xb + (iy1 * WW + ix0) * CC + ch0;
            const float* p11 = xb + (iy1 * WW + ix1) * CC + ch0;
            uint32_t* dst = (uint32_t*)&s_samp[sp * SSTR + ch0];
#pragma unroll
            for (int i = 0; i < 8; i++) {
                float4 a0 = *(const float4*)(p00 + i * 4);
                float4 a1 = *(const float4*)(p01 + i * 4);
                float4 a2 = *(const float4*)(p10 + i * 4);
                float4 a3 = *(const float4*)(p11 + i * 4);
                uint4 r;
                r.x = f2tf32(a0.x * w00 + a1.x * w01 + a2.x * w10 + a3.x * w11);
                r.y = f2tf32(a0.y * w00 + a1.y * w01 + a2.y * w10 + a3.y * w11);
                r.z = f2tf32(a0.z * w00 + a1.z * w01 + a2.z * w10 + a3.z * w11);
                r.w = f2tf32(a0.w * w00 + a1.w * w01 + a2.w * w10 + a3.w * w11);
                *(uint4*)(dst + i * 4) = r;
            }
        }
        __syncthreads();

        // warp-tiled tf32 MMA over 64 channels
        {
            const uint32_t* su = (const uint32_t*)s_samp;
            const uint32_t* wu = (const uint32_t*)s_w;
#pragma unroll
            for (int kk = 0; kk < 8; kk++) {
                int j = kk * 8;
                uint32_t a[2][4], bf[4][2];
#pragma unroll
                for (int mf = 0; mf < 2; mf++) {
                    int r0 = (p0 + mf * 16 + g) * SSTR + j + tg;
                    a[mf][0] = su[r0];
                    a[mf][1] = su[r0 + 8 * SSTR];
                    a[mf][2] = su[r0 + 4];
                    a[mf][3] = su[r0 + 8 * SSTR + 4];
                }
#pragma unroll
                for (int nt = 0; nt < 4; nt++) {
                    int c0 = (j + tg) * WSTR + n0 + nt * 8 + g;
                    bf[nt][0] = wu[c0];
                    bf[nt][1] = wu[c0 + 4 * WSTR];
                }
#pragma unroll
                for (int mf = 0; mf < 2; mf++)
#pragma unroll
                    for (int nt = 0; nt < 4; nt++)
                        MMA_TF32(acc[mf][nt], a[mf], bf[nt]);
            }
        }
    }

    // stage output as [o][p] in smem for coalesced NCHW stores
    __syncthreads();
    float* s_out = s_samp;   // 64*128 = 8192 floats <= 128*68
#pragma unroll
    for (int mf = 0; mf < 2; mf++)
#pragma unroll
        for (int nt = 0; nt < 4; nt++) {
            int row = p0 + mf * 16 + g;
            int col = n0 + nt * 8 + 2 * tg;
            s_out[col * PIX + row]             = acc[mf][nt][0];
            s_out[(col + 1) * PIX + row]       = acc[mf][nt][1];
            s_out[col * PIX + row + 8]         = acc[mf][nt][2];
            s_out[(col + 1) * PIX + row + 8]   = acc[mf][nt][3];
        }
    __syncthreads();

    float* ob = out + (size_t)(b * OO) * HWSZ + ho * WW;
    for (int i = tid; i < OO * PIX / 4; i += 256) {
        int o = i >> 5, p4 = i & 31;
        float4 v = ((const float4*)s_out)[i];
        float bo = bias[o];
        v.x += bo; v.y += bo; v.z += bo; v.w += bo;
        ((float4*)(ob + (size_t)o * HWSZ))[p4] = v;
    }
}

// ---------------- launch ----------------
#define DEFORM_SMEM ((CC*WSTR + PIX*SSTR + 4*PIX) * 4 + 4*PIX * 4)

extern "C" void kernel_launch(void* const* d_in, const int* in_sizes, int n_in,
                              void* d_out, int out_size) {
    const float* x     = (const float*)d_in[0];
    const float* w_off = (const float*)d_in[1];
    const float* b_off = (const float*)d_in[2];
    const float* w     = (const float*)d_in[3];
    const float* bias  = (const float*)d_in[4];
    float* out = (float*)d_out;

    (void)in_sizes; (void)n_in; (void)out_size;

    cudaFuncSetAttribute(k_deform, cudaFuncAttributeMaxDynamicSharedMemorySize, DEFORM_SMEM);

    dim3 tpb(32, 8);
    k_transpose<<<dim3(HWSZ / 32, CC / 32, BB), tpb>>>(x);
    k_wprep<<<(KK * CC * OO + 255) / 256, 256>>>(w, w_off);
    k_offconv<<<dim3(HH / 2, BB), 256>>>(b_off);
    k_deform<<<dim3(HH, BB), 256, DEFORM_SMEM>>>(bias, out);
}

// round 7
// speedup vs baseline: 2.5898x; 2.4226x over previous
#include <cuda_runtime.h>
#include <cstdint>

#define BB   8
#define CC   64
#define HH   128
#define WW   128
#define OO   64
#define OOFF 18
#define KK   9
#define HWSZ (HH*WW)

#define PIX  128   // pixels per block in k_deform (one full row)
#define SSTR 68    // sample smem pixel stride (floats) -> conflict-free A frags
#define WSTR 72    // weight smem row stride (floats)  -> conflict-free B frags

#define NOFF 24    // offset-conv N padded to 24 (3 x n8 tiles)
#define OSTR 24    // offset-conv weight smem stride (conflict-free: tg*24%32={0,24,16,8})
#define CSTR 68    // offset-conv staged-row stride

// ---------------- scratch (no allocations allowed) ----------------
__device__ __align__(16) float g_xt[BB*HWSZ*CC];        // x in NHWC
__device__ __align__(16) float g_off[BB*HWSZ*OOFF];     // offsets NHWC
__device__ __align__(16) float g_wt[KK*CC*OO];          // main weights [k][c][o], tf32
__device__ __align__(16) float g_wtoff2[KK*CC*NOFF];    // offset weights [k][c][24], tf32, zero-pad

__device__ __forceinline__ uint32_t f2tf32(float f) {
    uint32_t r;
    asm("cvt.rna.tf32.f32 %0, %1;" : "=r"(r) : "f"(f));
    return r;
}

#define MMA_TF32(d, a, b)                                                     \
    asm volatile("mma.sync.aligned.m16n8k8.row.col.f32.tf32.tf32.f32 "        \
                 "{%0,%1,%2,%3}, {%4,%5,%6,%7}, {%8,%9}, {%0,%1,%2,%3};"      \
                 : "+f"(d[0]), "+f"(d[1]), "+f"(d[2]), "+f"(d[3])             \
                 : "r"(a[0]), "r"(a[1]), "r"(a[2]), "r"(a[3]),                \
                   "r"(b[0]), "r"(b[1]))

// ---------------- kernel 1: NCHW -> NHWC transpose ----------------
__global__ void k_transpose(const float* __restrict__ x) {
    __shared__ float tile[32][33];
    int b   = blockIdx.z;
    int hw0 = blockIdx.x * 32;
    int c0  = blockIdx.y * 32;
    int tx = threadIdx.x, ty = threadIdx.y;
    const float* xp = x + (size_t)b * CC * HWSZ;
#pragma unroll
    for (int i = 0; i < 32; i += 8)
        tile[ty + i][tx] = xp[(c0 + ty + i) * HWSZ + hw0 + tx];
    __syncthreads();
    float* op = g_xt + (size_t)b * HWSZ * CC;
#pragma unroll
    for (int i = 0; i < 32; i += 8)
        op[(hw0 + ty + i) * CC + c0 + tx] = tile[tx][ty + i];
}

// ---------------- kernel 2: weight prep (transpose + tf32 round) ----------------
__global__ void k_wprep(const float* __restrict__ w, const float* __restrict__ woff) {
    int i = blockIdx.x * 256 + threadIdx.x;
    if (i < KK * CC * OO) {
        int k = i / (CC * OO);
        int r = i % (CC * OO);
        int c = r / OO;
        int o = r % OO;
        g_wt[i] = __uint_as_float(f2tf32(w[(o * CC + c) * KK + k]));
    }
    if (i < KK * CC * NOFF) {
        int k = i / (CC * NOFF);
        int r = i % (CC * NOFF);
        int c = r / NOFF;
        int o = r % NOFF;
        g_wtoff2[i] = (o < OOFF)
            ? __uint_as_float(f2tf32(woff[(o * CC + c) * KK + k]))
            : 0.f;
    }
}

// ---------------- kernel 3: offset conv via tf32 MMA ----------------
// Block = one output row (128 pixels). Stage 3 input rows one at a time
// (zero-padded cols) -> 9 taps are shifted-A GEMMs, K=64, N=24 (18 used).
// Warp tile: 16 pixels x 24 outputs.
__global__ __launch_bounds__(256) void k_offconv(const float* __restrict__ boff) {
    extern __shared__ __align__(16) float sm[];
    float* s_w   = sm;                       // [9][64][OSTR]  55.3 KB
    float* s_xr  = s_w + KK * CC * OSTR;     // [130][CSTR]    35.4 KB
    float* s_off = s_xr + 130 * CSTR;        // [128*18]        9.2 KB

    int tid  = threadIdx.x;
    int b    = blockIdx.y;
    int ho   = blockIdx.x;
    int lane = tid & 31;
    int wid  = tid >> 5;
    int g  = lane >> 2;
    int tg = lane & 3;
    int p0 = wid * 16;

    // stage all 9 taps' weights (already tf32, packed [k][c][24])
    {
        const float4* src = (const float4*)g_wtoff2;
        float4* dst = (float4*)s_w;
        for (int i = tid; i < KK * CC * NOFF / 4; i += 256) dst[i] = src[i];
    }

    float acc[3][4];
#pragma unroll
    for (int nt = 0; nt < 3; nt++)
#pragma unroll
        for (int c = 0; c < 4; c++) acc[nt][c] = 0.f;

#pragma unroll 1
    for (int ki = 0; ki < 3; ki++) {
        __syncthreads();   // previous ki's MMAs done with s_xr
        int y = ho - 1 + ki;
        if (y >= 0 && y < HH) {
            const float4* src = (const float4*)(g_xt + (size_t)(b * HWSZ + y * WW) * CC);
#pragma unroll
            for (int t = 0; t < 8; t++) {
                int idx = tid + t * 256;         // float4 over 128x64
                int p = idx >> 4, c4 = (idx & 15) * 4;
                float4 v = src[idx];
                uint4 r;
                r.x = f2tf32(v.x); r.y = f2tf32(v.y);
                r.z = f2tf32(v.z); r.w = f2tf32(v.w);
                *(uint4*)&s_xr[(p + 1) * CSTR + c4] = r;
            }
            if (tid < 32) {  // zero pad columns (buf rows 0 and 129)
                int row = (tid < 16) ? 0 : 129;
                int c4 = (tid & 15) * 4;
                *(float4*)&s_xr[row * CSTR + c4] = make_float4(0.f, 0.f, 0.f, 0.f);
            }
        } else {
            float4 z = make_float4(0.f, 0.f, 0.f, 0.f);
            for (int i = tid; i < 130 * CSTR / 4; i += 256)
                ((float4*)s_xr)[i] = z;
        }
        __syncthreads();

        const uint32_t* su = (const uint32_t*)s_xr;
#pragma unroll
        for (int kj = 0; kj < 3; kj++) {
            const uint32_t* wu = (const uint32_t*)&s_w[(ki * 3 + kj) * CC * OSTR];
            int rbase = (p0 + g + kj) * CSTR;
#pragma unroll
            for (int kk = 0; kk < 8; kk++) {
                int j = kk * 8;
                uint32_t a[4], bf[3][2];
                a[0] = su[rbase + j + tg];
                a[1] = su[rbase + 8 * CSTR + j + tg];
                a[2] = su[rbase + j + tg + 4];
                a[3] = su[rbase + 8 * CSTR + j + tg + 4];
#pragma unroll
                for (int nt = 0; nt < 3; nt++) {
                    int c0i = (j + tg) * OSTR + nt * 8 + g;
                    bf[nt][0] = wu[c0i];
                    bf[nt][1] = wu[c0i + 4 * OSTR];
                }
#pragma unroll
                for (int nt = 0; nt < 3; nt++)
                    MMA_TF32(acc[nt], a, bf[nt]);
            }
        }
    }

    // stage valid 18 outputs as packed [pix][18]
    __syncthreads();
#pragma unroll
    for (int nt = 0; nt < 3; nt++) {
        int col = nt * 8 + 2 * tg;
        if (col < OOFF) {
            s_off[(p0 + g) * OOFF + col]           = acc[nt][0];
            s_off[(p0 + g) * OOFF + col + 1]       = acc[nt][1];
            s_off[(p0 + g + 8) * OOFF + col]       = acc[nt][2];
            s_off[(p0 + g + 8) * OOFF + col + 1]   = acc[nt][3];
        }
    }
    __syncthreads();

    float* op = g_off + (size_t)(b * HWSZ + ho * WW) * OOFF;
    for (int i = tid; i < PIX * OOFF; i += 256)
        op[i] = s_off[i] + boff[i % OOFF];
}

// ---------------- kernel 4: deformable conv, tf32 mma.sync ----------------
// Block = one row (128 pixels) x 64 outputs. Per tap:
//   stage weights + bilinear params -> coalesced bilinear sample -> warp MMA.
__global__ __launch_bounds__(256) void k_deform(const float* __restrict__ bias,
                                                float* __restrict__ out) {
    extern __shared__ __align__(16) float smem[];
    float* s_w    = smem;                       // [CC][WSTR]
    float* s_samp = smem + CC * WSTR;           // [PIX][SSTR] (reused for out)
    float* s_w00  = s_samp + PIX * SSTR;
    float* s_w01  = s_w00 + PIX;
    float* s_w10  = s_w01 + PIX;
    float* s_w11  = s_w10 + PIX;
    int*   s_iy0  = (int*)(s_w11 + PIX);
    int*   s_iy1  = s_iy0 + PIX;
    int*   s_ix0  = s_iy1 + PIX;
    int*   s_ix1  = s_ix0 + PIX;

    int tid  = threadIdx.x;
    int b    = blockIdx.y;
    int ho   = blockIdx.x;
    int lane = tid & 31;
    int wid  = tid >> 5;

    int g  = lane >> 2;
    int tg = lane & 3;
    int p0 = (wid >> 1) * 32;
    int n0 = (wid & 1) * 32;

    // sampling mapping: 16 lanes cover one pixel's 64 channels contiguously
    int ph = lane >> 4;          // pixel-half within warp (0/1)
    int c4 = (lane & 15) * 4;    // channel float4 base

    float acc[2][4][4];
#pragma unroll
    for (int mf = 0; mf < 2; mf++)
#pragma unroll
        for (int nt = 0; nt < 4; nt++)
#pragma unroll
            for (int c = 0; c < 4; c++) acc[mf][nt][c] = 0.f;

#pragma unroll 1
    for (int k = 0; k < KK; k++) {
        __syncthreads();   // previous tap's GEMM done with s_w / s_samp

        // stage tap weights [64c][WSTR pad]
        {
            const float4* src = (const float4*)&g_wt[k * CC * OO];
#pragma unroll
            for (int t = 0; t < 4; t++) {
                int idx = tid + t * 256;
                int j = idx >> 4, o4 = (idx & 15) * 4;
                *(float4*)&s_w[j * WSTR + o4] = src[idx];
            }
        }

        // bilinear params for 128 pixels
        if (tid < PIX) {
            int p = tid;
            const float* offp = g_off + (size_t)(b * HWSZ + ho * WW + p) * OOFF + 2 * k;
            float dy = offp[0], dx = offp[1];
            int ki = k / 3, kj = k % 3;
            float py = (float)(ho - 1 + ki) + dy;
            float px = (float)(p - 1 + kj) + dx;
            float fy = floorf(py), fx = floorf(px);
            float wy = py - fy, wx = px - fx;
            int iy = (int)fy, ix = (int)fx;
            float vy0 = (iy >= 0 && iy < HH) ? 1.f : 0.f;
            float vy1 = (iy + 1 >= 0 && iy + 1 < HH) ? 1.f : 0.f;
            float vx0 = (ix >= 0 && ix < WW) ? 1.f : 0.f;
            float vx1 = (ix + 1 >= 0 && ix + 1 < WW) ? 1.f : 0.f;
            s_w00[p] = (1.f - wy) * (1.f - wx) * vy0 * vx0;
            s_w01[p] = (1.f - wy) * wx         * vy0 * vx1;
            s_w10[p] = wy         * (1.f - wx) * vy1 * vx0;
            s_w11[p] = wy         * wx         * vy1 * vx1;
            s_iy0[p] = min(max(iy, 0), HH - 1);
            s_iy1[p] = min(max(iy + 1, 0), HH - 1);
            s_ix0[p] = min(max(ix, 0), WW - 1);
            s_ix1[p] = min(max(ix + 1, 0), WW - 1);
        }
        __syncthreads();

        // coalesced bilinear sampling: 2 pixels/warp/iter, 16 lanes span 64 ch
        {
            const float* xb = g_xt + (size_t)b * HWSZ * CC;
#pragma unroll
            for (int it = 0; it < 8; it++) {
                int pp = it * 16 + wid * 2 + ph;
                int iy0 = s_iy0[pp], iy1 = s_iy1[pp], ix0 = s_ix0[pp], ix1 = s_ix1[pp];
                float w00 = s_w00[pp], w01 = s_w01[pp], w10 = s_w10[pp], w11 = s_w11[pp];
                float4 a0 = *(const float4*)(xb + (iy0 * WW + ix0) * CC + c4);
                float4 a1 = *(const float4*)(xb + (iy0 * WW + ix1) * CC + c4);
                float4 a2 = *(const float4*)(xb + (iy1 * WW + ix0) * CC + c4);
                float4 a3 = *(const float4*)(xb + (iy1 * WW + ix1) * CC + c4);
                uint4 r;
                r.x = f2tf32(a0.x * w00 + a1.x * w01 + a2.x * w10 + a3.x * w11);
                r.y = f2tf32(a0.y * w00 + a1.y * w01 + a2.y * w10 + a3.y * w11);
                r.z = f2tf32(a0.z * w00 + a1.z * w01 + a2.z * w10 + a3.z * w11);
                r.w = f2tf32(a0.w * w00 + a1.w * w01 + a2.w * w10 + a3.w * w11);
                *(uint4*)&s_samp[pp * SSTR + c4] = r;
            }
        }
        __syncthreads();

        // warp-tiled tf32 MMA over 64 channels (32 pix x 32 out per warp)
        {
            const uint32_t* su = (const uint32_t*)s_samp;
            const uint32_t* wu = (const uint32_t*)s_w;
#pragma unroll
            for (int kk = 0; kk < 8; kk++) {
                int j = kk * 8;
                uint32_t a[2][4], bf[4][2];
#pragma unroll
                for (int mf = 0; mf < 2; mf++) {
                    int r0 = (p0 + mf * 16 + g) * SSTR + j + tg;
                    a[mf][0] = su[r0];
                    a[mf][1] = su[r0 + 8 * SSTR];
                    a[mf][2] = su[r0 + 4];
                    a[mf][3] = su[r0 + 8 * SSTR + 4];
                }
#pragma unroll
                for (int nt = 0; nt < 4; nt++) {
                    int c0i = (j + tg) * WSTR + n0 + nt * 8 + g;
                    bf[nt][0] = wu[c0i];
                    bf[nt][1] = wu[c0i + 4 * WSTR];
                }
#pragma unroll
                for (int mf = 0; mf < 2; mf++)
#pragma unroll
                    for (int nt = 0; nt < 4; nt++)
                        MMA_TF32(acc[mf][nt], a[mf], bf[nt]);
            }
        }
    }

    // stage output as [o][p] for coalesced NCHW stores
    __syncthreads();
    float* s_out = s_samp;
#pragma unroll
    for (int mf = 0; mf < 2; mf++)
#pragma unroll
        for (int nt = 0; nt < 4; nt++) {
            int row = p0 + mf * 16 + g;
            int col = n0 + nt * 8 + 2 * tg;
            s_out[col * PIX + row]           = acc[mf][nt][0];
            s_out[(col + 1) * PIX + row]     = acc[mf][nt][1];
            s_out[col * PIX + row + 8]       = acc[mf][nt][2];
            s_out[(col + 1) * PIX + row + 8] = acc[mf][nt][3];
        }
    __syncthreads();

    float* ob = out + (size_t)(b * OO) * HWSZ + ho * WW;
    for (int i = tid; i < OO * PIX / 4; i += 256) {
        int o = i >> 5, p4 = i & 31;
        float4 v = ((const float4*)s_out)[i];
        float bo = bias[o];
        v.x += bo; v.y += bo; v.z += bo; v.w += bo;
        ((float4*)(ob + (size_t)o * HWSZ))[p4] = v;
    }
}

// ---------------- launch ----------------
#define DEFORM_SMEM ((CC*WSTR + PIX*SSTR + 4*PIX) * 4 + 4*PIX * 4)
#define OFFC_SMEM   ((KK*CC*OSTR + 130*CSTR + PIX*OOFF) * 4)

extern "C" void kernel_launch(void* const* d_in, const int* in_sizes, int n_in,
                              void* d_out, int out_size) {
    const float* x     = (const float*)d_in[0];
    const float* w_off = (const float*)d_in[1];
    const float* b_off = (const float*)d_in[2];
    const float* w     = (const float*)d_in[3];
    const float* bias  = (const float*)d_in[4];
    float* out = (float*)d_out;

    (void)in_sizes; (void)n_in; (void)out_size;

    cudaFuncSetAttribute(k_deform,  cudaFuncAttributeMaxDynamicSharedMemorySize, DEFORM_SMEM);
    cudaFuncSetAttribute(k_offconv, cudaFuncAttributeMaxDynamicSharedMemorySize, OFFC_SMEM);

    dim3 tpb(32, 8);
    k_transpose<<<dim3(HWSZ / 32, CC / 32, BB), tpb>>>(x);
    k_wprep<<<(KK * CC * OO + 255) / 256, 256>>>(w, w_off);
    k_offconv<<<dim3(HH, BB), 256, OFFC_SMEM>>>(b_off);
    k_deform<<<dim3(HH, BB), 256, DEFORM_SMEM>>>(bias, out);
}

// round 8
// speedup vs baseline: 2.5910x; 1.0005x over previous
#include <cuda_runtime.h>
#include <cstdint>

#define BB   8
#define CC   64
#define HH   128
#define WW   128
#define OO   64
#define OOFF 18
#define KK   9
#define HWSZ (HH*WW)

#define PIX  128   // pixels per block in k_deform (one full row)
#define SSTR 68    // sample smem pixel stride (floats) -> conflict-free A frags
#define WSTR 72    // weight smem row stride (floats)  -> conflict-free B frags

#define NOFF 24    // offset-conv N padded to 24 (3 x n8 tiles)
#define OSTR 24    // offset-conv weight smem stride (conflict-free: tg*24%32={0,24,16,8})
#define CSTR 68    // offset-conv staged-row stride

// ---------------- scratch (no allocations allowed) ----------------
__device__ __align__(16) float g_xt[BB*HWSZ*CC];        // x in NHWC
__device__ __align__(16) float g_off[BB*HWSZ*OOFF];     // offsets NHWC
__device__ __align__(16) float g_wt[KK*CC*OO];          // main weights [k][c][o], tf32
__device__ __align__(16) float g_wtoff2[KK*CC*NOFF];    // offset weights [k][c][24], tf32, zero-pad

__device__ __forceinline__ uint32_t f2tf32(float f) {
    uint32_t r;
    asm("cvt.rna.tf32.f32 %0, %1;" : "=r"(r) : "f"(f));
    return r;
}

#define MMA_TF32(d, a, b)                                                     \
    asm volatile("mma.sync.aligned.m16n8k8.row.col.f32.tf32.tf32.f32 "        \
                 "{%0,%1,%2,%3}, {%4,%5,%6,%7}, {%8,%9}, {%0,%1,%2,%3};"      \
                 : "+f"(d[0]), "+f"(d[1]), "+f"(d[2]), "+f"(d[3])             \
                 : "r"(a[0]), "r"(a[1]), "r"(a[2]), "r"(a[3]),                \
                   "r"(b[0]), "r"(b[1]))

// ---------------- kernel 1: NCHW -> NHWC transpose ----------------
__global__ void k_transpose(const float* __restrict__ x) {
    __shared__ float tile[32][33];
    int b   = blockIdx.z;
    int hw0 = blockIdx.x * 32;
    int c0  = blockIdx.y * 32;
    int tx = threadIdx.x, ty = threadIdx.y;
    const float* xp = x + (size_t)b * CC * HWSZ;
#pragma unroll
    for (int i = 0; i < 32; i += 8)
        tile[ty + i][tx] = xp[(c0 + ty + i) * HWSZ + hw0 + tx];
    __syncthreads();
    float* op = g_xt + (size_t)b * HWSZ * CC;
#pragma unroll
    for (int i = 0; i < 32; i += 8)
        op[(hw0 + ty + i) * CC + c0 + tx] = tile[tx][ty + i];
}

// ---------------- kernel 2: weight prep (transpose + tf32 round) ----------------
__global__ void k_wprep(const float* __restrict__ w, const float* __restrict__ woff) {
    int i = blockIdx.x * 256 + threadIdx.x;
    if (i < KK * CC * OO) {
        int k = i / (CC * OO);
        int r = i % (CC * OO);
        int c = r / OO;
        int o = r % OO;
        g_wt[i] = __uint_as_float(f2tf32(w[(o * CC + c) * KK + k]));
    }
    if (i < KK * CC * NOFF) {
        int k = i / (CC * NOFF);
        int r = i % (CC * NOFF);
        int c = r / NOFF;
        int o = r % NOFF;
        g_wtoff2[i] = (o < OOFF)
            ? __uint_as_float(f2tf32(woff[(o * CC + c) * KK + k]))
            : 0.f;
    }
}

// ---------------- kernel 3: offset conv via tf32 MMA ----------------
// Block = one output row (128 pixels). Stage 3 input rows one at a time
// (zero-padded cols) -> 9 taps are shifted-A GEMMs, K=64, N=24 (18 used).
// Warp tile: 16 pixels x 24 outputs.
__global__ __launch_bounds__(256) void k_offconv(const float* __restrict__ boff) {
    extern __shared__ __align__(16) float sm[];
    float* s_w   = sm;                       // [9][64][OSTR]  55.3 KB
    float* s_xr  = s_w + KK * CC * OSTR;     // [130][CSTR]    35.4 KB
    float* s_off = s_xr + 130 * CSTR;        // [128*18]        9.2 KB

    int tid  = threadIdx.x;
    int b    = blockIdx.y;
    int ho   = blockIdx.x;
    int lane = tid & 31;
    int wid  = tid >> 5;
    int g  = lane >> 2;
    int tg = lane & 3;
    int p0 = wid * 16;

    // stage all 9 taps' weights (already tf32, packed [k][c][24])
    {
        const float4* src = (const float4*)g_wtoff2;
        float4* dst = (float4*)s_w;
        for (int i = tid; i < KK * CC * NOFF / 4; i += 256) dst[i] = src[i];
    }

    float acc[3][4];
#pragma unroll
    for (int nt = 0; nt < 3; nt++)
#pragma unroll
        for (int c = 0; c < 4; c++) acc[nt][c] = 0.f;

#pragma unroll 1
    for (int ki = 0; ki < 3; ki++) {
        __syncthreads();   // previous ki's MMAs done with s_xr
        int y = ho - 1 + ki;
        if (y >= 0 && y < HH) {
            const float4* src = (const float4*)(g_xt + (size_t)(b * HWSZ + y * WW) * CC);
#pragma unroll
            for (int t = 0; t < 8; t++) {
                int idx = tid + t * 256;         // float4 over 128x64
                int p = idx >> 4, c4 = (idx & 15) * 4;
                float4 v = src[idx];
                uint4 r;
                r.x = f2tf32(v.x); r.y = f2tf32(v.y);
                r.z = f2tf32(v.z); r.w = f2tf32(v.w);
                *(uint4*)&s_xr[(p + 1) * CSTR + c4] = r;
            }
            if (tid < 32) {  // zero pad columns (buf rows 0 and 129)
                int row = (tid < 16) ? 0 : 129;
                int c4 = (tid & 15) * 4;
                *(float4*)&s_xr[row * CSTR + c4] = make_float4(0.f, 0.f, 0.f, 0.f);
            }
        } else {
            float4 z = make_float4(0.f, 0.f, 0.f, 0.f);
            for (int i = tid; i < 130 * CSTR / 4; i += 256)
                ((float4*)s_xr)[i] = z;
        }
        __syncthreads();

        const uint32_t* su = (const uint32_t*)s_xr;
#pragma unroll
        for (int kj = 0; kj < 3; kj++) {
            const uint32_t* wu = (const uint32_t*)&s_w[(ki * 3 + kj) * CC * OSTR];
            int rbase = (p0 + g + kj) * CSTR;
#pragma unroll
            for (int kk = 0; kk < 8; kk++) {
                int j = kk * 8;
                uint32_t a[4], bf[3][2];
                a[0] = su[rbase + j + tg];
                a[1] = su[rbase + 8 * CSTR + j + tg];
                a[2] = su[rbase + j + tg + 4];
                a[3] = su[rbase + 8 * CSTR + j + tg + 4];
#pragma unroll
                for (int nt = 0; nt < 3; nt++) {
                    int c0i = (j + tg) * OSTR + nt * 8 + g;
                    bf[nt][0] = wu[c0i];
                    bf[nt][1] = wu[c0i + 4 * OSTR];
                }
#pragma unroll
                for (int nt = 0; nt < 3; nt++)
                    MMA_TF32(acc[nt], a, bf[nt]);
            }
        }
    }

    // stage valid 18 outputs as packed [pix][18]
    __syncthreads();
#pragma unroll
    for (int nt = 0; nt < 3; nt++) {
        int col = nt * 8 + 2 * tg;
        if (col < OOFF) {
            s_off[(p0 + g) * OOFF + col]           = acc[nt][0];
            s_off[(p0 + g) * OOFF + col + 1]       = acc[nt][1];
            s_off[(p0 + g + 8) * OOFF + col]       = acc[nt][2];
            s_off[(p0 + g + 8) * OOFF + col + 1]   = acc[nt][3];
        }
    }
    __syncthreads();

    float* op = g_off + (size_t)(b * HWSZ + ho * WW) * OOFF;
    for (int i = tid; i < PIX * OOFF; i += 256)
        op[i] = s_off[i] + boff[i % OOFF];
}

// ---------------- kernel 4: deformable conv, tf32 mma.sync ----------------
// Block = one row (128 pixels) x 64 outputs. Per tap:
//   stage weights + bilinear params -> coalesced bilinear sample -> warp MMA.
__global__ __launch_bounds__(256) void k_deform(const float* __restrict__ bias,
                                                float* __restrict__ out) {
    extern __shared__ __align__(16) float smem[];
    float* s_w    = smem;                       // [CC][WSTR]
    float* s_samp = smem + CC * WSTR;           // [PIX][SSTR] (reused for out)
    float* s_w00  = s_samp + PIX * SSTR;
    float* s_w01  = s_w00 + PIX;
    float* s_w10  = s_w01 + PIX;
    float* s_w11  = s_w10 + PIX;
    int*   s_iy0  = (int*)(s_w11 + PIX);
    int*   s_iy1  = s_iy0 + PIX;
    int*   s_ix0  = s_iy1 + PIX;
    int*   s_ix1  = s_ix0 + PIX;

    int tid  = threadIdx.x;
    int b    = blockIdx.y;
    int ho   = blockIdx.x;
    int lane = tid & 31;
    int wid  = tid >> 5;

    int g  = lane >> 2;
    int tg = lane & 3;
    int p0 = (wid >> 1) * 32;
    int n0 = (wid & 1) * 32;

    // sampling mapping: 16 lanes cover one pixel's 64 channels contiguously
    int ph = lane >> 4;          // pixel-half within warp (0/1)
    int c4 = (lane & 15) * 4;    // channel float4 base

    float acc[2][4][4];
#pragma unroll
    for (int mf = 0; mf < 2; mf++)
#pragma unroll
        for (int nt = 0; nt < 4; nt++)
#pragma unroll
            for (int c = 0; c < 4; c++) acc[mf][nt][c] = 0.f;

#pragma unroll 1
    for (int k = 0; k < KK; k++) {
        __syncthreads();   // previous tap's GEMM done with s_w / s_samp

        // stage tap weights [64c][WSTR pad]
        {
            const float4* src = (const float4*)&g_wt[k * CC * OO];
#pragma unroll
            for (int t = 0; t < 4; t++) {
                int idx = tid + t * 256;
                int j = idx >> 4, o4 = (idx & 15) * 4;
                *(float4*)&s_w[j * WSTR + o4] = src[idx];
            }
        }

        // bilinear params for 128 pixels
        if (tid < PIX) {
            int p = tid;
            const float* offp = g_off + (size_t)(b * HWSZ + ho * WW + p) * OOFF + 2 * k;
            float dy = offp[0], dx = offp[1];
            int ki = k / 3, kj = k % 3;
            float py = (float)(ho - 1 + ki) + dy;
            float px = (float)(p - 1 + kj) + dx;
            float fy = floorf(py), fx = floorf(px);
            float wy = py - fy, wx = px - fx;
            int iy = (int)fy, ix = (int)fx;
            float vy0 = (iy >= 0 && iy < HH) ? 1.f : 0.f;
            float vy1 = (iy + 1 >= 0 && iy + 1 < HH) ? 1.f : 0.f;
            float vx0 = (ix >= 0 && ix < WW) ? 1.f : 0.f;
            float vx1 = (ix + 1 >= 0 && ix + 1 < WW) ? 1.f : 0.f;
            s_w00[p] = (1.f - wy) * (1.f - wx) * vy0 * vx0;
            s_w01[p] = (1.f - wy) * wx         * vy0 * vx1;
            s_w10[p] = wy         * (1.f - wx) * vy1 * vx0;
            s_w11[p] = wy         * wx         * vy1 * vx1;
            s_iy0[p] = min(max(iy, 0), HH - 1);
            s_iy1[p] = min(max(iy + 1, 0), HH - 1);
            s_ix0[p] = min(max(ix, 0), WW - 1);
            s_ix1[p] = min(max(ix + 1, 0), WW - 1);
        }
        __syncthreads();

        // coalesced bilinear sampling: 2 pixels/warp/iter, 16 lanes span 64 ch
        {
            const float* xb = g_xt + (size_t)b * HWSZ * CC;
#pragma unroll
            for (int it = 0; it < 8; it++) {
                int pp = it * 16 + wid * 2 + ph;
                int iy0 = s_iy0[pp], iy1 = s_iy1[pp], ix0 = s_ix0[pp], ix1 = s_ix1[pp];
                float w00 = s_w00[pp], w01 = s_w01[pp], w10 = s_w10[pp], w11 = s_w11[pp];
                float4 a0 = *(const float4*)(xb + (iy0 * WW + ix0) * CC + c4);
                float4 a1 = *(const float4*)(xb + (iy0 * WW + ix1) * CC + c4);
                float4 a2 = *(const float4*)(xb + (iy1 * WW + ix0) * CC + c4);
                float4 a3 = *(const float4*)(xb + (iy1 * WW + ix1) * CC + c4);
                uint4 r;
                r.x = f2tf32(a0.x * w00 + a1.x * w01 + a2.x * w10 + a3.x * w11);
                r.y = f2tf32(a0.y * w00 + a1.y * w01 + a2.y * w10 + a3.y * w11);
                r.z = f2tf32(a0.z * w00 + a1.z * w01 + a2.z * w10 + a3.z * w11);
                r.w = f2tf32(a0.w * w00 + a1.w * w01 + a2.w * w10 + a3.w * w11);
                *(uint4*)&s_samp[pp * SSTR + c4] = r;
            }
        }
        __syncthreads();

        // warp-tiled tf32 MMA over 64 channels (32 pix x 32 out per warp)
        {
            const uint32_t* su = (const uint32_t*)s_samp;
            const uint32_t* wu = (const uint32_t*)s_w;
#pragma unroll
            for (int kk = 0; kk < 8; kk++) {
                int j = kk * 8;
                uint32_t a[2][4], bf[4][2];
#pragma unroll
                for (int mf = 0; mf < 2; mf++) {
                    int r0 = (p0 + mf * 16 + g) * SSTR + j + tg;
                    a[mf][0] = su[r0];
                    a[mf][1] = su[r0 + 8 * SSTR];
                    a[mf][2] = su[r0 + 4];
                    a[mf][3] = su[r0 + 8 * SSTR + 4];
                }
#pragma unroll
                for (int nt = 0; nt < 4; nt++) {
                    int c0i = (j + tg) * WSTR + n0 + nt * 8 + g;
                    bf[nt][0] = wu[c0i];
                    bf[nt][1] = wu[c0i + 4 * WSTR];
                }
#pragma unroll
                for (int mf = 0; mf < 2; mf++)
#pragma unroll
                    for (int nt = 0; nt < 4; nt++)
                        MMA_TF32(acc[mf][nt], a[mf], bf[nt]);
            }
        }
    }

    // stage output as [o][p] for coalesced NCHW stores
    __syncthreads();
    float* s_out = s_samp;
#pragma unroll
    for (int mf = 0; mf < 2; mf++)
#pragma unroll
        for (int nt = 0; nt < 4; nt++) {
            int row = p0 + mf * 16 + g;
            int col = n0 + nt * 8 + 2 * tg;
            s_out[col * PIX + row]           = acc[mf][nt][0];
            s_out[(col + 1) * PIX + row]     = acc[mf][nt][1];
            s_out[col * PIX + row + 8]       = acc[mf][nt][2];
            s_out[(col + 1) * PIX + row + 8] = acc[mf][nt][3];
        }
    __syncthreads();

    float* ob = out + (size_t)(b * OO) * HWSZ + ho * WW;
    for (int i = tid; i < OO * PIX / 4; i += 256) {
        int o = i >> 5, p4 = i & 31;
        float4 v = ((const float4*)s_out)[i];
        float bo = bias[o];
        v.x += bo; v.y += bo; v.z += bo; v.w += bo;
        ((float4*)(ob + (size_t)o * HWSZ))[p4] = v;
    }
}

// ---------------- launch ----------------
#define DEFORM_SMEM ((CC*WSTR + PIX*SSTR + 4*PIX) * 4 + 4*PIX * 4)
#define OFFC_SMEM   ((KK*CC*OSTR + 130*CSTR + PIX*OOFF) * 4)

extern "C" void kernel_launch(void* const* d_in, const int* in_sizes, int n_in,
                              void* d_out, int out_size) {
    const float* x     = (const float*)d_in[0];
    const float* w_off = (const float*)d_in[1];
    const float* b_off = (const float*)d_in[2];
    const float* w     = (const float*)d_in[3];
    const float* bias  = (const float*)d_in[4];
    float* out = (float*)d_out;

    (void)in_sizes; (void)n_in; (void)out_size;

    cudaFuncSetAttribute(k_deform,  cudaFuncAttributeMaxDynamicSharedMemorySize, DEFORM_SMEM);
    cudaFuncSetAttribute(k_offconv, cudaFuncAttributeMaxDynamicSharedMemorySize, OFFC_SMEM);

    dim3 tpb(32, 8);
    k_transpose<<<dim3(HWSZ / 32, CC / 32, BB), tpb>>>(x);
    k_wprep<<<(KK * CC * OO + 255) / 256, 256>>>(w, w_off);
    k_offconv<<<dim3(HH, BB), 256, OFFC_SMEM>>>(b_off);
    k_deform<<<dim3(HH, BB), 256, DEFORM_SMEM>>>(bias, out);
}

// round 9
// speedup vs baseline: 3.7069x; 1.4307x over previous
#include <cuda_runtime.h>
#include <cuda_fp16.h>
#include <cstdint>

#define BB   8
#define CC   64
#define HH   128
#define WW   128
#define OO   64
#define OOFF 18
#define KK   9
#define HWSZ (HH*WW)

#define PIX  128   // pixels per block in k_deform (one full row)
#define SSH  72    // s_samp pixel stride (halves) -> 144B rows, conflict-free ldmatrix
#define WSH  72    // s_w k-row stride (halves)

#define NOFF 24    // offset-conv N padded to 24 (3 x n8 tiles)
#define OSTR 24    // offset-conv weight smem stride (floats)
#define CSTR 68    // offset-conv staged-row stride (floats)

// ---------------- scratch (no allocations allowed) ----------------
__device__ __align__(16) __half g_xth[BB*HWSZ*CC];      // x in NHWC, fp16 (16.8MB)
__device__ __align__(16) float  g_off[BB*HWSZ*OOFF];    // offsets NHWC fp32
__device__ __align__(16) __half g_wth[KK*CC*OO];        // main weights [k][c][o] fp16
__device__ __align__(16) float  g_wtoff2[KK*CC*NOFF];   // offset weights [k][c][24] tf32

__device__ __forceinline__ uint32_t f2tf32(float f) {
    uint32_t r;
    asm("cvt.rna.tf32.f32 %0, %1;" : "=r"(r) : "f"(f));
    return r;
}
__device__ __forceinline__ uint32_t smem_u32(const void* p) {
    return (uint32_t)__cvta_generic_to_shared(p);
}

#define MMA_TF32(d, a, b)                                                     \
    asm volatile("mma.sync.aligned.m16n8k8.row.col.f32.tf32.tf32.f32 "        \
                 "{%0,%1,%2,%3}, {%4,%5,%6,%7}, {%8,%9}, {%0,%1,%2,%3};"      \
                 : "+f"(d[0]), "+f"(d[1]), "+f"(d[2]), "+f"(d[3])             \
                 : "r"(a[0]), "r"(a[1]), "r"(a[2]), "r"(a[3]),                \
                   "r"(b[0]), "r"(b[1]))

#define MMA_F16(d, a, b)                                                      \
    asm volatile("mma.sync.aligned.m16n8k16.row.col.f32.f16.f16.f32 "         \
                 "{%0,%1,%2,%3}, {%4,%5,%6,%7}, {%8,%9}, {%0,%1,%2,%3};"      \
                 : "+f"(d[0]), "+f"(d[1]), "+f"(d[2]), "+f"(d[3])             \
                 : "r"(a[0]), "r"(a[1]), "r"(a[2]), "r"(a[3]),                \
                   "r"(b[0]), "r"(b[1]))

#define LDSM_X4(r0, r1, r2, r3, addr)                                         \
    asm volatile("ldmatrix.sync.aligned.m8n8.x4.shared.b16 {%0,%1,%2,%3}, [%4];" \
                 : "=r"(r0), "=r"(r1), "=r"(r2), "=r"(r3) : "r"(addr))

#define LDSM_X4_T(r0, r1, r2, r3, addr)                                       \
    asm volatile("ldmatrix.sync.aligned.m8n8.x4.trans.shared.b16 {%0,%1,%2,%3}, [%4];" \
                 : "=r"(r0), "=r"(r1), "=r"(r2), "=r"(r3) : "r"(addr))

// ---------------- kernel 1: NCHW fp32 -> NHWC fp16 ----------------
// Block covers 32 hw x 64 c; half2 stores give full 128B output lines.
__global__ void k_transpose(const float* __restrict__ x) {
    __shared__ float tile[64][33];
    int b   = blockIdx.z;
    int hw0 = blockIdx.x * 32;
    int c0  = blockIdx.y * 64;
    int tx = threadIdx.x, ty = threadIdx.y;
    const float* xp = x + (size_t)b * CC * HWSZ;
#pragma unroll
    for (int i = 0; i < 64; i += 8)
        tile[ty + i][tx] = xp[(size_t)(c0 + ty + i) * HWSZ + hw0 + tx];
    __syncthreads();
    __half2* op = (__half2*)(g_xth + (size_t)b * HWSZ * CC);
#pragma unroll
    for (int i = 0; i < 32; i += 8) {
        int row = ty + i;
        float lo = tile[2 * tx][row], hi = tile[2 * tx + 1][row];
        op[((size_t)(hw0 + row) * CC + c0) / 2 + tx] = __floats2half2_rn(lo, hi);
    }
}

// ---------------- kernel 2: weight prep ----------------
__global__ void k_wprep(const float* __restrict__ w, const float* __restrict__ woff) {
    int i = blockIdx.x * 256 + threadIdx.x;
    if (i < KK * CC * OO) {
        int k = i / (CC * OO);
        int r = i % (CC * OO);
        int c = r / OO;
        int o = r % OO;
        g_wth[i] = __float2half_rn(w[(o * CC + c) * KK + k]);
    }
    if (i < KK * CC * NOFF) {
        int k = i / (CC * NOFF);
        int r = i % (CC * NOFF);
        int c = r / NOFF;
        int o = r % NOFF;
        g_wtoff2[i] = (o < OOFF)
            ? __uint_as_float(f2tf32(woff[(o * CC + c) * KK + k]))
            : 0.f;
    }
}

// ---------------- kernel 3: offset conv via tf32 MMA ----------------
__global__ __launch_bounds__(256) void k_offconv(const float* __restrict__ boff) {
    extern __shared__ __align__(16) float sm[];
    float* s_w   = sm;                       // [9][64][OSTR]
    float* s_xr  = s_w + KK * CC * OSTR;     // [130][CSTR]
    float* s_off = s_xr + 130 * CSTR;        // [128*18]

    int tid  = threadIdx.x;
    int b    = blockIdx.y;
    int ho   = blockIdx.x;
    int lane = tid & 31;
    int wid  = tid >> 5;
    int g  = lane >> 2;
    int tg = lane & 3;
    int p0 = wid * 16;

    {
        const float4* src = (const float4*)g_wtoff2;
        float4* dst = (float4*)s_w;
        for (int i = tid; i < KK * CC * NOFF / 4; i += 256) dst[i] = src[i];
    }

    float acc[3][4];
#pragma unroll
    for (int nt = 0; nt < 3; nt++)
#pragma unroll
        for (int c = 0; c < 4; c++) acc[nt][c] = 0.f;

#pragma unroll 1
    for (int ki = 0; ki < 3; ki++) {
        __syncthreads();
        int y = ho - 1 + ki;
        if (y >= 0 && y < HH) {
            const uint4* src = (const uint4*)(g_xth + (size_t)(b * HWSZ + y * WW) * CC);
#pragma unroll
            for (int t = 0; t < 4; t++) {
                int idx = tid + t * 256;       // 1024 chunks of 8 halves
                int p = idx >> 3, c8 = (idx & 7) * 8;
                uint4 q = src[idx];
                const __half2* h2 = (const __half2*)&q;
                uint4 r0, r1;
                float2 f;
                f = __half22float2(h2[0]); r0.x = f2tf32(f.x); r0.y = f2tf32(f.y);
                f = __half22float2(h2[1]); r0.z = f2tf32(f.x); r0.w = f2tf32(f.y);
                f = __half22float2(h2[2]); r1.x = f2tf32(f.x); r1.y = f2tf32(f.y);
                f = __half22float2(h2[3]); r1.z = f2tf32(f.x); r1.w = f2tf32(f.y);
                *(uint4*)&s_xr[(p + 1) * CSTR + c8]     = r0;
                *(uint4*)&s_xr[(p + 1) * CSTR + c8 + 4] = r1;
            }
            if (tid < 32) {
                int row = (tid < 16) ? 0 : 129;
                int c4 = (tid & 15) * 4;
                *(float4*)&s_xr[row * CSTR + c4] = make_float4(0.f, 0.f, 0.f, 0.f);
            }
        } else {
            float4 z = make_float4(0.f, 0.f, 0.f, 0.f);
            for (int i = tid; i < 130 * CSTR / 4; i += 256)
                ((float4*)s_xr)[i] = z;
        }
        __syncthreads();

        const uint32_t* su = (const uint32_t*)s_xr;
#pragma unroll
        for (int kj = 0; kj < 3; kj++) {
            const uint32_t* wu = (const uint32_t*)&s_w[(ki * 3 + kj) * CC * OSTR];
            int rbase = (p0 + g + kj) * CSTR;
#pragma unroll
            for (int kk = 0; kk < 8; kk++) {
                int j = kk * 8;
                uint32_t a[4], bf[3][2];
                a[0] = su[rbase + j + tg];
                a[1] = su[rbase + 8 * CSTR + j + tg];
                a[2] = su[rbase + j + tg + 4];
                a[3] = su[rbase + 8 * CSTR + j + tg + 4];
#pragma unroll
                for (int nt = 0; nt < 3; nt++) {
                    int c0i = (j + tg) * OSTR + nt * 8 + g;
                    bf[nt][0] = wu[c0i];
                    bf[nt][1] = wu[c0i + 4 * OSTR];
                }
#pragma unroll
                for (int nt = 0; nt < 3; nt++)
                    MMA_TF32(acc[nt], a, bf[nt]);
            }
        }
    }

    __syncthreads();
#pragma unroll
    for (int nt = 0; nt < 3; nt++) {
        int col = nt * 8 + 2 * tg;
        if (col < OOFF) {
            s_off[(p0 + g) * OOFF + col]         = acc[nt][0];
            s_off[(p0 + g) * OOFF + col + 1]     = acc[nt][1];
            s_off[(p0 + g + 8) * OOFF + col]     = acc[nt][2];
            s_off[(p0 + g + 8) * OOFF + col + 1] = acc[nt][3];
        }
    }
    __syncthreads();

    float* op = g_off + (size_t)(b * HWSZ + ho * WW) * OOFF;
    for (int i = tid; i < PIX * OOFF; i += 256)
        op[i] = s_off[i] + boff[i % OOFF];
}

// ---------------- kernel 4: deformable conv, fp16 mma + ldmatrix ----------------
// Block = 128 pixels x 64 outputs. Per tap: stage fp16 weights + bilinear params,
// gather fp16 corners (coalesced) -> fp16 sampled tile -> ldmatrix + m16n8k16.
__global__ __launch_bounds__(256) void k_deform(const float* __restrict__ bias,
                                                float* __restrict__ out) {
    extern __shared__ __align__(16) char smraw[];
    __half* s_w    = (__half*)smraw;                       // [64][WSH]  9216 B
    __half* s_samp = (__half*)(smraw + 9216);              // [128][SSH] 18432 B
    float*  s_w00  = (float*)(smraw + 27648);              // params: 4x128 f + 4x128 i
    float*  s_w01  = s_w00 + PIX;
    float*  s_w10  = s_w01 + PIX;
    float*  s_w11  = s_w10 + PIX;
    int*    s_iy0  = (int*)(s_w11 + PIX);
    int*    s_iy1  = s_iy0 + PIX;
    int*    s_ix0  = s_iy1 + PIX;
    int*    s_ix1  = s_ix0 + PIX;
    float*  s_out  = (float*)smraw;                        // epilogue reuse, 32768 B

    int tid  = threadIdx.x;
    int b    = blockIdx.y;
    int ho   = blockIdx.x;
    int lane = tid & 31;
    int wid  = tid >> 5;

    int g  = lane >> 2;
    int tg = lane & 3;
    int p0 = (wid >> 1) * 32;
    int n0 = (wid & 1) * 32;

    // sampling mapping: 8 lanes cover one pixel's 64 ch (128B), 4 pixels/warp/iter
    int ppi  = lane >> 3;        // pixel-in-group 0..3
    int cid8 = (lane & 7) * 8;   // channel base (8 ch, 16B)

    float acc[2][4][4];
#pragma unroll
    for (int mf = 0; mf < 2; mf++)
#pragma unroll
        for (int nt = 0; nt < 4; nt++)
#pragma unroll
            for (int c = 0; c < 4; c++) acc[mf][nt][c] = 0.f;

#pragma unroll 1
    for (int k = 0; k < KK; k++) {
        __syncthreads();   // previous tap's MMAs done with s_w / s_samp

        // stage tap weights fp16 [64c][WSH]
        {
            const uint4* src = (const uint4*)(g_wth + k * CC * OO);
#pragma unroll
            for (int t = 0; t < 2; t++) {
                int idx = tid + t * 256;          // 512 chunks of 8 halves
                int j = idx >> 3, o8 = (idx & 7) * 8;
                *(uint4*)&s_w[j * WSH + o8] = src[idx];
            }
        }

        // bilinear params for 128 pixels
        if (tid < PIX) {
            int p = tid;
            const float* offp = g_off + (size_t)(b * HWSZ + ho * WW + p) * OOFF + 2 * k;
            float dy = offp[0], dx = offp[1];
            int ki = k / 3, kj = k % 3;
            float py = (float)(ho - 1 + ki) + dy;
            float px = (float)(p - 1 + kj) + dx;
            float fy = floorf(py), fx = floorf(px);
            float wy = py - fy, wx = px - fx;
            int iy = (int)fy, ix = (int)fx;
            float vy0 = (iy >= 0 && iy < HH) ? 1.f : 0.f;
            float vy1 = (iy + 1 >= 0 && iy + 1 < HH) ? 1.f : 0.f;
            float vx0 = (ix >= 0 && ix < WW) ? 1.f : 0.f;
            float vx1 = (ix + 1 >= 0 && ix + 1 < WW) ? 1.f : 0.f;
            s_w00[p] = (1.f - wy) * (1.f - wx) * vy0 * vx0;
            s_w01[p] = (1.f - wy) * wx         * vy0 * vx1;
            s_w10[p] = wy         * (1.f - wx) * vy1 * vx0;
            s_w11[p] = wy         * wx         * vy1 * vx1;
            s_iy0[p] = min(max(iy, 0), HH - 1);
            s_iy1[p] = min(max(iy + 1, 0), HH - 1);
            s_ix0[p] = min(max(ix, 0), WW - 1);
            s_ix1[p] = min(max(ix + 1, 0), WW - 1);
        }
        __syncthreads();

        // coalesced fp16 bilinear sampling: 4 pixels/warp/iter
        {
            const __half* xb = g_xth + (size_t)b * HWSZ * CC;
#pragma unroll
            for (int it = 0; it < 4; it++) {
                int pp = it * 32 + wid * 4 + ppi;
                int iy0 = s_iy0[pp], iy1 = s_iy1[pp], ix0 = s_ix0[pp], ix1 = s_ix1[pp];
                float w00 = s_w00[pp], w01 = s_w01[pp], w10 = s_w10[pp], w11 = s_w11[pp];
                uint4 q00 = *(const uint4*)(xb + (iy0 * WW + ix0) * CC + cid8);
                uint4 q01 = *(const uint4*)(xb + (iy0 * WW + ix1) * CC + cid8);
                uint4 q10 = *(const uint4*)(xb + (iy1 * WW + ix0) * CC + cid8);
                uint4 q11 = *(const uint4*)(xb + (iy1 * WW + ix1) * CC + cid8);
                const __half2* h00 = (const __half2*)&q00;
                const __half2* h01 = (const __half2*)&q01;
                const __half2* h10 = (const __half2*)&q10;
                const __half2* h11 = (const __half2*)&q11;
                uint4 r;
                __half2* ro = (__half2*)&r;
#pragma unroll
                for (int u = 0; u < 4; u++) {
                    float2 f00 = __half22float2(h00[u]);
                    float2 f01 = __half22float2(h01[u]);
                    float2 f10 = __half22float2(h10[u]);
                    float2 f11 = __half22float2(h11[u]);
                    float2 rv;
                    rv.x = f00.x * w00 + f01.x * w01 + f10.x * w10 + f11.x * w11;
                    rv.y = f00.y * w00 + f01.y * w01 + f10.y * w10 + f11.y * w11;
                    ro[u] = __float22half2_rn(rv);
                }
                *(uint4*)&s_samp[pp * SSH + cid8] = r;
            }
        }
        __syncthreads();

        // fp16 MMA over 64 channels: 4 k16 chunks, ldmatrix fragments
        {
#pragma unroll
            for (int kk = 0; kk < 4; kk++) {
                int j = kk * 16;
                uint32_t A[2][4], Bf[4][2];
#pragma unroll
                for (int mf = 0; mf < 2; mf++) {
                    uint32_t addr = smem_u32(
                        &s_samp[(p0 + mf * 16 + (lane & 15)) * SSH + j + ((lane >> 4) << 3)]);
                    LDSM_X4(A[mf][0], A[mf][1], A[mf][2], A[mf][3], addr);
                }
#pragma unroll
                for (int q = 0; q < 2; q++) {   // nt pairs (0,1) and (2,3)
                    uint32_t addr = smem_u32(
                        &s_w[(j + (lane & 8) + (lane & 7)) * WSH
                             + n0 + (q * 2 + (lane >> 4)) * 8]);
                    LDSM_X4_T(Bf[2 * q][0], Bf[2 * q][1], Bf[2 * q + 1][0], Bf[2 * q + 1][1], addr);
                }
#pragma unroll
                for (int mf = 0; mf < 2; mf++)
#pragma unroll
                    for (int nt = 0; nt < 4; nt++)
                        MMA_F16(acc[mf][nt], A[mf], Bf[nt]);
            }
        }
    }

    // stage output as [o][p] for coalesced NCHW stores
    __syncthreads();
#pragma unroll
    for (int mf = 0; mf < 2; mf++)
#pragma unroll
        for (int nt = 0; nt < 4; nt++) {
            int row = p0 + mf * 16 + g;
            int col = n0 + nt * 8 + 2 * tg;
            s_out[col * PIX + row]           = acc[mf][nt][0];
            s_out[(col + 1) * PIX + row]     = acc[mf][nt][1];
            s_out[col * PIX + row + 8]       = acc[mf][nt][2];
            s_out[(col + 1) * PIX + row + 8] = acc[mf][nt][3];
        }
    __syncthreads();

    float* ob = out + (size_t)(b * OO) * HWSZ + ho * WW;
    for (int i = tid; i < OO * PIX / 4; i += 256) {
        int o = i >> 5, p4 = i & 31;
        float4 v = ((const float4*)s_out)[i];
        float bo = bias[o];
        v.x += bo; v.y += bo; v.z += bo; v.w += bo;
        ((float4*)(ob + (size_t)o * HWSZ))[p4] = v;
    }
}

// ---------------- launch ----------------
#define DEFORM_SMEM 32768
#define OFFC_SMEM   ((KK*CC*OSTR + 130*CSTR + PIX*OOFF) * 4)

extern "C" void kernel_launch(void* const* d_in, const int* in_sizes, int n_in,
                              void* d_out, int out_size) {
    const float* x     = (const float*)d_in[0];
    const float* w_off = (const float*)d_in[1];
    const float* b_off = (const float*)d_in[2];
    const float* w     = (const float*)d_in[3];
    const float* bias  = (const float*)d_in[4];
    float* out = (float*)d_out;

    (void)in_sizes; (void)n_in; (void)out_size;

    cudaFuncSetAttribute(k_offconv, cudaFuncAttributeMaxDynamicSharedMemorySize, OFFC_SMEM);

    dim3 tpb(32, 8);
    k_transpose<<<dim3(HWSZ / 32, CC / 64, BB), tpb>>>(x);
    k_wprep<<<(KK * CC * OO + 255) / 256, 256>>>(w, w_off);
    k_offconv<<<dim3(HH, BB), 256, OFFC_SMEM>>>(b_off);
    k_deform<<<dim3(HH, BB), 256, DEFORM_SMEM>>>(bias, out);
}

// round 10
// speedup vs baseline: 3.9738x; 1.0720x over previous
#include <cuda_runtime.h>
#include <cuda_fp16.h>
#include <cstdint>

#define BB   8
#define CC   64
#define HH   128
#define WW   128
#define OO   64
#define OOFF 18
#define KK   9
#define HWSZ (HH*WW)

#define PIX  128   // pixels per block in k_deform (one full row)
#define SSH  72    // s_samp pixel stride (halves) -> 144B rows, conflict-free ldmatrix
#define WSH  72    // s_w k-row stride (halves)

#define NOFF 24    // offset-conv N padded to 24 (3 x n8 tiles)
#define OSTR 24    // offset-conv weight smem stride (floats)
#define CSTR 68    // offset-conv staged-row stride (floats)

// ---------------- scratch (no allocations allowed) ----------------
__device__ __align__(16) __half g_xth[BB*HWSZ*CC];      // x in NHWC, fp16
__device__ __align__(16) float  g_off[BB*HWSZ*OOFF];    // offsets NHWC fp32
__device__ __align__(16) __half g_wth[KK*CC*OO];        // main weights [k][c][o] fp16
__device__ __align__(16) float  g_wtoff2[KK*CC*NOFF];   // offset weights [k][c][24] tf32

__device__ __forceinline__ uint32_t f2tf32(float f) {
    uint32_t r;
    asm("cvt.rna.tf32.f32 %0, %1;" : "=r"(r) : "f"(f));
    return r;
}
__device__ __forceinline__ uint32_t smem_u32(const void* p) {
    return (uint32_t)__cvta_generic_to_shared(p);
}

#define MMA_TF32(d, a, b)                                                     \
    asm volatile("mma.sync.aligned.m16n8k8.row.col.f32.tf32.tf32.f32 "        \
                 "{%0,%1,%2,%3}, {%4,%5,%6,%7}, {%8,%9}, {%0,%1,%2,%3};"      \
                 : "+f"(d[0]), "+f"(d[1]), "+f"(d[2]), "+f"(d[3])             \
                 : "r"(a[0]), "r"(a[1]), "r"(a[2]), "r"(a[3]),                \
                   "r"(b[0]), "r"(b[1]))

#define MMA_F16(d, a, b)                                                      \
    asm volatile("mma.sync.aligned.m16n8k16.row.col.f32.f16.f16.f32 "         \
                 "{%0,%1,%2,%3}, {%4,%5,%6,%7}, {%8,%9}, {%0,%1,%2,%3};"      \
                 : "+f"(d[0]), "+f"(d[1]), "+f"(d[2]), "+f"(d[3])             \
                 : "r"(a[0]), "r"(a[1]), "r"(a[2]), "r"(a[3]),                \
                   "r"(b[0]), "r"(b[1]))

#define LDSM_X4(r0, r1, r2, r3, addr)                                         \
    asm volatile("ldmatrix.sync.aligned.m8n8.x4.shared.b16 {%0,%1,%2,%3}, [%4];" \
                 : "=r"(r0), "=r"(r1), "=r"(r2), "=r"(r3) : "r"(addr))

#define LDSM_X4_T(r0, r1, r2, r3, addr)                                       \
    asm volatile("ldmatrix.sync.aligned.m8n8.x4.trans.shared.b16 {%0,%1,%2,%3}, [%4];" \
                 : "=r"(r0), "=r"(r1), "=r"(r2), "=r"(r3) : "r"(addr))

// ---------------- kernel 1: NCHW fp32 -> NHWC fp16 ----------------
__global__ void k_transpose(const float* __restrict__ x) {
    __shared__ float tile[64][33];
    int b   = blockIdx.z;
    int hw0 = blockIdx.x * 32;
    int c0  = blockIdx.y * 64;
    int tx = threadIdx.x, ty = threadIdx.y;
    const float* xp = x + (size_t)b * CC * HWSZ;
#pragma unroll
    for (int i = 0; i < 64; i += 8)
        tile[ty + i][tx] = xp[(size_t)(c0 + ty + i) * HWSZ + hw0 + tx];
    __syncthreads();
    __half2* op = (__half2*)(g_xth + (size_t)b * HWSZ * CC);
#pragma unroll
    for (int i = 0; i < 32; i += 8) {
        int row = ty + i;
        float lo = tile[2 * tx][row], hi = tile[2 * tx + 1][row];
        op[((size_t)(hw0 + row) * CC + c0) / 2 + tx] = __floats2half2_rn(lo, hi);
    }
}

// ---------------- kernel 2: weight prep ----------------
__global__ void k_wprep(const float* __restrict__ w, const float* __restrict__ woff) {
    int i = blockIdx.x * 256 + threadIdx.x;
    if (i < KK * CC * OO) {
        int k = i / (CC * OO);
        int r = i % (CC * OO);
        int c = r / OO;
        int o = r % OO;
        g_wth[i] = __float2half_rn(w[(o * CC + c) * KK + k]);
    }
    if (i < KK * CC * NOFF) {
        int k = i / (CC * NOFF);
        int r = i % (CC * NOFF);
        int c = r / NOFF;
        int o = r % NOFF;
        g_wtoff2[i] = (o < OOFF)
            ? __uint_as_float(f2tf32(woff[(o * CC + c) * KK + k]))
            : 0.f;
    }
}

// ---------------- kernel 3: offset conv via tf32 MMA (unchanged) ----------------
__global__ __launch_bounds__(256) void k_offconv(const float* __restrict__ boff) {
    extern __shared__ __align__(16) float sm[];
    float* s_w   = sm;                       // [9][64][OSTR]
    float* s_xr  = s_w + KK * CC * OSTR;     // [130][CSTR]
    float* s_off = s_xr + 130 * CSTR;        // [128*18]

    int tid  = threadIdx.x;
    int b    = blockIdx.y;
    int ho   = blockIdx.x;
    int lane = tid & 31;
    int wid  = tid >> 5;
    int g  = lane >> 2;
    int tg = lane & 3;
    int p0 = wid * 16;

    {
        const float4* src = (const float4*)g_wtoff2;
        float4* dst = (float4*)s_w;
        for (int i = tid; i < KK * CC * NOFF / 4; i += 256) dst[i] = src[i];
    }

    float acc[3][4];
#pragma unroll
    for (int nt = 0; nt < 3; nt++)
#pragma unroll
        for (int c = 0; c < 4; c++) acc[nt][c] = 0.f;

#pragma unroll 1
    for (int ki = 0; ki < 3; ki++) {
        __syncthreads();
        int y = ho - 1 + ki;
        if (y >= 0 && y < HH) {
            const uint4* src = (const uint4*)(g_xth + (size_t)(b * HWSZ + y * WW) * CC);
#pragma unroll
            for (int t = 0; t < 4; t++) {
                int idx = tid + t * 256;
                int p = idx >> 3, c8 = (idx & 7) * 8;
                uint4 q = src[idx];
                const __half2* h2 = (const __half2*)&q;
                uint4 r0, r1;
                float2 f;
                f = __half22float2(h2[0]); r0.x = f2tf32(f.x); r0.y = f2tf32(f.y);
                f = __half22float2(h2[1]); r0.z = f2tf32(f.x); r0.w = f2tf32(f.y);
                f = __half22float2(h2[2]); r1.x = f2tf32(f.x); r1.y = f2tf32(f.y);
                f = __half22float2(h2[3]); r1.z = f2tf32(f.x); r1.w = f2tf32(f.y);
                *(uint4*)&s_xr[(p + 1) * CSTR + c8]     = r0;
                *(uint4*)&s_xr[(p + 1) * CSTR + c8 + 4] = r1;
            }
            if (tid < 32) {
                int row = (tid < 16) ? 0 : 129;
                int c4 = (tid & 15) * 4;
                *(float4*)&s_xr[row * CSTR + c4] = make_float4(0.f, 0.f, 0.f, 0.f);
            }
        } else {
            float4 z = make_float4(0.f, 0.f, 0.f, 0.f);
            for (int i = tid; i < 130 * CSTR / 4; i += 256)
                ((float4*)s_xr)[i] = z;
        }
        __syncthreads();

        const uint32_t* su = (const uint32_t*)s_xr;
#pragma unroll
        for (int kj = 0; kj < 3; kj++) {
            const uint32_t* wu = (const uint32_t*)&s_w[(ki * 3 + kj) * CC * OSTR];
            int rbase = (p0 + g + kj) * CSTR;
#pragma unroll
            for (int kk = 0; kk < 8; kk++) {
                int j = kk * 8;
                uint32_t a[4], bf[3][2];
                a[0] = su[rbase + j + tg];
                a[1] = su[rbase + 8 * CSTR + j + tg];
                a[2] = su[rbase + j + tg + 4];
                a[3] = su[rbase + 8 * CSTR + j + tg + 4];
#pragma unroll
                for (int nt = 0; nt < 3; nt++) {
                    int c0i = (j + tg) * OSTR + nt * 8 + g;
                    bf[nt][0] = wu[c0i];
                    bf[nt][1] = wu[c0i + 4 * OSTR];
                }
#pragma unroll
                for (int nt = 0; nt < 3; nt++)
                    MMA_TF32(acc[nt], a, bf[nt]);
            }
        }
    }

    __syncthreads();
#pragma unroll
    for (int nt = 0; nt < 3; nt++) {
        int col = nt * 8 + 2 * tg;
        if (col < OOFF) {
            s_off[(p0 + g) * OOFF + col]         = acc[nt][0];
            s_off[(p0 + g) * OOFF + col + 1]     = acc[nt][1];
            s_off[(p0 + g + 8) * OOFF + col]     = acc[nt][2];
            s_off[(p0 + g + 8) * OOFF + col + 1] = acc[nt][3];
        }
    }
    __syncthreads();

    float* op = g_off + (size_t)(b * HWSZ + ho * WW) * OOFF;
    for (int i = tid; i < PIX * OOFF; i += 256)
        op[i] = s_off[i] + boff[i % OOFF];
}

// ---------------- kernel 4: deformable conv, fp16 mma + hoisted params ----------------
// Phase 0: stage offset row coalesced, precompute ALL 9 taps' bilinear params
//          (element offsets + packed half2 weights).
// Per tap: {stage weights + HFMA2 bilinear sample} -> sync -> ldmatrix + m16n8k16.
__global__ __launch_bounds__(256, 3) void k_deform(const float* __restrict__ bias,
                                                   float* __restrict__ out) {
    extern __shared__ __align__(16) char smraw[];
    __half*  s_w    = (__half*)smraw;                       // [64][WSH]   9216 B
    __half*  s_samp = (__half*)(smraw + 9216);              // [128][SSH] 18432 B
    int*     s_c00  = (int*)(smraw + 27648);                // [9*128] each
    int*     s_c01  = s_c00 + KK * PIX;
    int*     s_c10  = s_c01 + KK * PIX;
    int*     s_c11  = s_c10 + KK * PIX;
    __half2* s_wA   = (__half2*)(s_c11 + KK * PIX);         // (w00,w01)
    __half2* s_wB   = s_wA + KK * PIX;                      // (w10,w11)
    float*   s_offrow = (float*)(smraw + 9216);             // phase-0 alias of s_samp
    float*   s_out  = (float*)smraw;                        // epilogue alias, 32768 B

    int tid  = threadIdx.x;
    int b    = blockIdx.y;
    int ho   = blockIdx.x;
    int lane = tid & 31;
    int wid  = tid >> 5;

    int g  = lane >> 2;
    int tg = lane & 3;
    int p0 = (wid >> 1) * 32;
    int n0 = (wid & 1) * 32;

    int ppi  = lane >> 3;        // pixel-in-group 0..3 (sampling)
    int cid8 = (lane & 7) * 8;   // channel base (8 ch, 16B)

    // ---- phase 0: offsets row -> smem (coalesced), then all params ----
    {
        const float4* osrc = (const float4*)(g_off + (size_t)(b * HWSZ + ho * WW) * OOFF);
        for (int i = tid; i < PIX * OOFF / 4; i += 256)
            ((float4*)s_offrow)[i] = osrc[i];
    }
    __syncthreads();
    for (int i = tid; i < KK * PIX; i += 256) {
        int p = i & (PIX - 1);
        int k = i >> 7;
        float dy = s_offrow[p * OOFF + 2 * k];
        float dx = s_offrow[p * OOFF + 2 * k + 1];
        int ki = k / 3, kj = k % 3;
        float py = (float)(ho - 1 + ki) + dy;
        float px = (float)(p - 1 + kj) + dx;
        float fy = floorf(py), fx = floorf(px);
        float wy = py - fy, wx = px - fx;
        int iy = (int)fy, ix = (int)fx;
        float vy0 = (iy >= 0 && iy < HH) ? 1.f : 0.f;
        float vy1 = (iy + 1 >= 0 && iy + 1 < HH) ? 1.f : 0.f;
        float vx0 = (ix >= 0 && ix < WW) ? 1.f : 0.f;
        float vx1 = (ix + 1 >= 0 && ix + 1 < WW) ? 1.f : 0.f;
        float w00 = (1.f - wy) * (1.f - wx) * vy0 * vx0;
        float w01 = (1.f - wy) * wx         * vy0 * vx1;
        float w10 = wy         * (1.f - wx) * vy1 * vx0;
        float w11 = wy         * wx         * vy1 * vx1;
        int iy0 = min(max(iy, 0), HH - 1);
        int iy1 = min(max(iy + 1, 0), HH - 1);
        int ix0 = min(max(ix, 0), WW - 1);
        int ix1 = min(max(ix + 1, 0), WW - 1);
        s_c00[i] = (iy0 * WW + ix0) * CC;
        s_c01[i] = (iy0 * WW + ix1) * CC;
        s_c10[i] = (iy1 * WW + ix0) * CC;
        s_c11[i] = (iy1 * WW + ix1) * CC;
        s_wA[i] = __floats2half2_rn(w00, w01);
        s_wB[i] = __floats2half2_rn(w10, w11);
    }

    float acc[2][4][4];
#pragma unroll
    for (int mf = 0; mf < 2; mf++)
#pragma unroll
        for (int nt = 0; nt < 4; nt++)
#pragma unroll
            for (int c = 0; c < 4; c++) acc[mf][nt][c] = 0.f;

#pragma unroll 1
    for (int k = 0; k < KK; k++) {
        __syncthreads();   // previous tap's MMAs done with s_w / s_samp (also fences phase 0)

        // stage tap weights fp16 [64c][WSH]
        {
            const uint4* src = (const uint4*)(g_wth + k * CC * OO);
#pragma unroll
            for (int t = 0; t < 2; t++) {
                int idx = tid + t * 256;
                int j = idx >> 3, o8 = (idx & 7) * 8;
                *(uint4*)&s_w[j * WSH + o8] = src[idx];
            }
        }

        // HFMA2 bilinear sampling: 4 pixels/warp/iter, precomputed params
        {
            const __half* xb = g_xth + (size_t)b * HWSZ * CC;
#pragma unroll
            for (int it = 0; it < 4; it++) {
                int pp  = it * 32 + wid * 4 + ppi;
                int idx = k * PIX + pp;
                int c00 = s_c00[idx], c01 = s_c01[idx], c10 = s_c10[idx], c11 = s_c11[idx];
                __half2 wA = s_wA[idx], wB = s_wB[idx];
                __half2 w00v = __low2half2(wA),  w01v = __high2half2(wA);
                __half2 w10v = __low2half2(wB),  w11v = __high2half2(wB);
                uint4 q00 = *(const uint4*)(xb + c00 + cid8);
                uint4 q01 = *(const uint4*)(xb + c01 + cid8);
                uint4 q10 = *(const uint4*)(xb + c10 + cid8);
                uint4 q11 = *(const uint4*)(xb + c11 + cid8);
                const __half2* h00 = (const __half2*)&q00;
                const __half2* h01 = (const __half2*)&q01;
                const __half2* h10 = (const __half2*)&q10;
                const __half2* h11 = (const __half2*)&q11;
                uint4 r;
                __half2* ro = (__half2*)&r;
#pragma unroll
                for (int u = 0; u < 4; u++)
                    ro[u] = __hfma2(h11[u], w11v,
                            __hfma2(h10[u], w10v,
                            __hfma2(h01[u], w01v,
                            __hmul2(h00[u], w00v))));
                *(uint4*)&s_samp[pp * SSH + cid8] = r;
            }
        }
        __syncthreads();

        // fp16 MMA over 64 channels: 4 k16 chunks, ldmatrix fragments
        {
#pragma unroll
            for (int kk = 0; kk < 4; kk++) {
                int j = kk * 16;
                uint32_t A[2][4], Bf[4][2];
#pragma unroll
                for (int mf = 0; mf < 2; mf++) {
                    uint32_t addr = smem_u32(
                        &s_samp[(p0 + mf * 16 + (lane & 15)) * SSH + j + ((lane >> 4) << 3)]);
                    LDSM_X4(A[mf][0], A[mf][1], A[mf][2], A[mf][3], addr);
                }
#pragma unroll
                for (int q = 0; q < 2; q++) {
                    uint32_t addr = smem_u32(
                        &s_w[(j + (lane & 8) + (lane & 7)) * WSH
                             + n0 + (q * 2 + (lane >> 4)) * 8]);
                    LDSM_X4_T(Bf[2 * q][0], Bf[2 * q][1], Bf[2 * q + 1][0], Bf[2 * q + 1][1], addr);
                }
#pragma unroll
                for (int mf = 0; mf < 2; mf++)
#pragma unroll
                    for (int nt = 0; nt < 4; nt++)
                        MMA_F16(acc[mf][nt], A[mf], Bf[nt]);
            }
        }
    }

    // stage output as [o][p] for coalesced NCHW stores
    __syncthreads();
#pragma unroll
    for (int mf = 0; mf < 2; mf++)
#pragma unroll
        for (int nt = 0; nt < 4; nt++) {
            int row = p0 + mf * 16 + g;
            int col = n0 + nt * 8 + 2 * tg;
            s_out[col * PIX + row]           = acc[mf][nt][0];
            s_out[(col + 1) * PIX + row]     = acc[mf][nt][1];
            s_out[col * PIX + row + 8]       = acc[mf][nt][2];
            s_out[(col + 1) * PIX + row + 8] = acc[mf][nt][3];
        }
    __syncthreads();

    float* ob = out + (size_t)(b * OO) * HWSZ + ho * WW;
    for (int i = tid; i < OO * PIX / 4; i += 256) {
        int o = i >> 5, p4 = i & 31;
        float4 v = ((const float4*)s_out)[i];
        float bo = bias[o];
        v.x += bo; v.y += bo; v.z += bo; v.w += bo;
        ((float4*)(ob + (size_t)o * HWSZ))[p4] = v;
    }
}

// ---------------- launch ----------------
#define DEFORM_SMEM (9216 + 18432 + 4 * KK * PIX * 4 + 2 * KK * PIX * 4)  // 55296
#define OFFC_SMEM   ((KK*CC*OSTR + 130*CSTR + PIX*OOFF) * 4)

extern "C" void kernel_launch(void* const* d_in, const int* in_sizes, int n_in,
                              void* d_out, int out_size) {
    const float* x     = (const float*)d_in[0];
    const float* w_off = (const float*)d_in[1];
    const float* b_off = (const float*)d_in[2];
    const float* w     = (const float*)d_in[3];
    const float* bias  = (const float*)d_in[4];
    float* out = (float*)d_out;

    (void)in_sizes; (void)n_in; (void)out_size;

    cudaFuncSetAttribute(k_offconv, cudaFuncAttributeMaxDynamicSharedMemorySize, OFFC_SMEM);
    cudaFuncSetAttribute(k_deform,  cudaFuncAttributeMaxDynamicSharedMemorySize, DEFORM_SMEM);

    dim3 tpb(32, 8);
    k_transpose<<<dim3(HWSZ / 32, CC / 64, BB), tpb>>>(x);
    k_wprep<<<(KK * CC * OO + 255) / 256, 256>>>(w, w_off);
    k_offconv<<<dim3(HH, BB), 256, OFFC_SMEM>>>(b_off);
    k_deform<<<dim3(HH, BB), 256, DEFORM_SMEM>>>(bias, out);
}

// round 11
// speedup vs baseline: 4.6233x; 1.1635x over previous
#include <cuda_runtime.h>
#include <cuda_fp16.h>
#include <cstdint>

#define BB   8
#define CC   64
#define HH   128
#define WW   128
#define OO   64
#define OOFF 18
#define KK   9
#define HWSZ (HH*WW)

#define PIX  128   // pixels per block in k_deform (one full row)
#define SSH  72    // s_samp pixel stride (halves) -> 144B rows, conflict-free ldmatrix
#define WSH  72    // s_w k-row stride (halves)
#define WBUFH (CC*WSH)    // 4608 halves per weight buffer
#define SBUFH (PIX*SSH)   // 9216 halves per sample buffer

#define NOFF 24    // offset-conv N padded to 24 (3 x n8 tiles)
#define XSTR 136   // offset-conv staged-row stride (halves)
#define WOSTR 72   // offset-conv weight k-stride (halves), layout [tap][n][k]

// ---------------- scratch (no allocations allowed) ----------------
__device__ __align__(16) __half g_xth[BB*HWSZ*CC];      // x in NHWC, fp16
__device__ __align__(16) float  g_off[BB*HWSZ*OOFF];    // offsets NHWC fp32
__device__ __align__(16) __half g_wth[KK*CC*OO];        // main weights [k][c][o] fp16
__device__ __align__(16) __half g_wtoffh[KK*NOFF*CC];   // offset weights [k][n][c] fp16, zero-pad

__device__ __forceinline__ uint32_t smem_u32(const void* p) {
    return (uint32_t)__cvta_generic_to_shared(p);
}

#define MMA_F16(d, a, b)                                                      \
    asm volatile("mma.sync.aligned.m16n8k16.row.col.f32.f16.f16.f32 "         \
                 "{%0,%1,%2,%3}, {%4,%5,%6,%7}, {%8,%9}, {%0,%1,%2,%3};"      \
                 : "+f"(d[0]), "+f"(d[1]), "+f"(d[2]), "+f"(d[3])             \
                 : "r"(a[0]), "r"(a[1]), "r"(a[2]), "r"(a[3]),                \
                   "r"(b[0]), "r"(b[1]))

#define LDSM_X4(r0, r1, r2, r3, addr)                                         \
    asm volatile("ldmatrix.sync.aligned.m8n8.x4.shared.b16 {%0,%1,%2,%3}, [%4];" \
                 : "=r"(r0), "=r"(r1), "=r"(r2), "=r"(r3) : "r"(addr))

#define LDSM_X4_T(r0, r1, r2, r3, addr)                                       \
    asm volatile("ldmatrix.sync.aligned.m8n8.x4.trans.shared.b16 {%0,%1,%2,%3}, [%4];" \
                 : "=r"(r0), "=r"(r1), "=r"(r2), "=r"(r3) : "r"(addr))

// ---------------- kernel 1: NCHW fp32 -> NHWC fp16 ----------------
__global__ void k_transpose(const float* __restrict__ x) {
    __shared__ float tile[64][33];
    int b   = blockIdx.z;
    int hw0 = blockIdx.x * 32;
    int c0  = blockIdx.y * 64;
    int tx = threadIdx.x, ty = threadIdx.y;
    const float* xp = x + (size_t)b * CC * HWSZ;
#pragma unroll
    for (int i = 0; i < 64; i += 8)
        tile[ty + i][tx] = xp[(size_t)(c0 + ty + i) * HWSZ + hw0 + tx];
    __syncthreads();
    __half2* op = (__half2*)(g_xth + (size_t)b * HWSZ * CC);
#pragma unroll
    for (int i = 0; i < 32; i += 8) {
        int row = ty + i;
        float lo = tile[2 * tx][row], hi = tile[2 * tx + 1][row];
        op[((size_t)(hw0 + row) * CC + c0) / 2 + tx] = __floats2half2_rn(lo, hi);
    }
}

// ---------------- kernel 2: weight prep ----------------
__global__ void k_wprep(const float* __restrict__ w, const float* __restrict__ woff) {
    int i = blockIdx.x * 256 + threadIdx.x;
    if (i < KK * CC * OO) {
        int k = i / (CC * OO);
        int r = i % (CC * OO);
        int c = r / OO;
        int o = r % OO;
        g_wth[i] = __float2half_rn(w[(o * CC + c) * KK + k]);
    }
    if (i < KK * NOFF * CC) {
        int t = i / (NOFF * CC);
        int r = i % (NOFF * CC);
        int n = r / CC;
        int c = r % CC;
        g_wtoffh[i] = (n < OOFF)
            ? __float2half_rn(woff[(n * CC + c) * KK + t])
            : __float2half_rn(0.f);
    }
}

// ---------------- kernel 3: offset conv via fp16 MMA ----------------
// Block = one output row. Stage 3 input rows (fp16, raw copy, zero-pad cols);
// 9 taps = shifted-A GEMMs, K=64 (4 k16 chunks), N=24 (18 used).
__global__ __launch_bounds__(256) void k_offconv(const float* __restrict__ boff) {
    extern __shared__ __align__(16) char smo[];
    __half* s_wo  = (__half*)smo;                        // [9][24][WOSTR] 31104 B
    __half* s_xr  = (__half*)(smo + 31104);              // [130][XSTR]    35360 B
    float*  s_off = (float*)(smo + 31104 + 35360);       // [128*18]        9216 B

    int tid  = threadIdx.x;
    int b    = blockIdx.y;
    int ho   = blockIdx.x;
    int lane = tid & 31;
    int wid  = tid >> 5;
    int g  = lane >> 2;
    int tg = lane & 3;
    int p0 = wid * 16;

    // stage all 9 taps' weights [t][n][k] with stride WOSTR
    {
        const uint4* src = (const uint4*)g_wtoffh;
        for (int i = tid; i < KK * NOFF * CC / 8; i += 256) {
            int tn = i >> 3, c8 = (i & 7) * 8;           // tn = t*24 + n
            *(uint4*)&s_wo[tn * WOSTR + c8] = src[i];
        }
    }

    float acc[3][4];
#pragma unroll
    for (int nt = 0; nt < 3; nt++)
#pragma unroll
        for (int c = 0; c < 4; c++) acc[nt][c] = 0.f;

#pragma unroll 1
    for (int ki = 0; ki < 3; ki++) {
        __syncthreads();
        int y = ho - 1 + ki;
        if (y >= 0 && y < HH) {
            const uint4* src = (const uint4*)(g_xth + (size_t)(b * HWSZ + y * WW) * CC);
#pragma unroll
            for (int t = 0; t < 4; t++) {
                int idx = tid + t * 256;                 // 1024 uint4 = 128 rows x 8
                int p = idx >> 3, c8 = (idx & 7) * 8;
                *(uint4*)&s_xr[(p + 1) * XSTR + c8] = src[idx];
            }
            if (tid < 16) {   // zero pad rows 0 and 129 (first 64 ch)
                int row = (tid >> 3) ? 129 : 0;
                int c8 = (tid & 7) * 8;
                *(uint4*)&s_xr[row * XSTR + c8] = make_uint4(0, 0, 0, 0);
            }
        } else {
            uint4 z = make_uint4(0, 0, 0, 0);
            for (int i = tid; i < 130 * XSTR / 8; i += 256)
                ((uint4*)s_xr)[i] = z;
        }
        __syncthreads();

#pragma unroll
        for (int kj = 0; kj < 3; kj++) {
            const __half* wt = &s_wo[(ki * 3 + kj) * NOFF * WOSTR];
            int rbase = (p0 + g + kj) * XSTR;
#pragma unroll
            for (int kk = 0; kk < 4; kk++) {
                int j = kk * 16;
                uint32_t a[4], bf[3][2];
                a[0] = *(const uint32_t*)&s_xr[rbase + j + 2 * tg];
                a[1] = *(const uint32_t*)&s_xr[rbase + 8 * XSTR + j + 2 * tg];
                a[2] = *(const uint32_t*)&s_xr[rbase + j + 2 * tg + 8];
                a[3] = *(const uint32_t*)&s_xr[rbase + 8 * XSTR + j + 2 * tg + 8];
#pragma unroll
                for (int nt = 0; nt < 3; nt++) {
                    int n = nt * 8 + g;
                    bf[nt][0] = *(const uint32_t*)&wt[n * WOSTR + j + 2 * tg];
                    bf[nt][1] = *(const uint32_t*)&wt[n * WOSTR + j + 2 * tg + 8];
                }
#pragma unroll
                for (int nt = 0; nt < 3; nt++)
                    MMA_F16(acc[nt], a, bf[nt]);
            }
        }
    }

    __syncthreads();
#pragma unroll
    for (int nt = 0; nt < 3; nt++) {
        int col = nt * 8 + 2 * tg;
        if (col < OOFF) {
            s_off[(p0 + g) * OOFF + col]         = acc[nt][0];
            s_off[(p0 + g) * OOFF + col + 1]     = acc[nt][1];
            s_off[(p0 + g + 8) * OOFF + col]     = acc[nt][2];
            s_off[(p0 + g + 8) * OOFF + col + 1] = acc[nt][3];
        }
    }
    __syncthreads();

    float* op = g_off + (size_t)(b * HWSZ + ho * WW) * OOFF;
    for (int i = tid; i < PIX * OOFF; i += 256)
        op[i] = s_off[i] + boff[i % OOFF];
}

// ---------------- kernel 4: deformable conv, pipelined fp16 MMA ----------------
struct Pref {
    uint4 q00, q01, q10, q11;
    __half2 wA, wB;
    int pp;
};

__device__ __forceinline__ void gather_issue(
    Pref& P, int kidx, int pp, const __half* __restrict__ xb, int cid8,
    const int* s_cA, const int* s_cB, const __half2* s_wA, const __half2* s_wB)
{
    int idx = kidx * PIX + pp;
    int cA = s_cA[idx], cB = s_cB[idx];
    P.wA = s_wA[idx];
    P.wB = s_wB[idx];
    P.pp = pp;
    P.q00 = *(const uint4*)(xb + (cA & 0xFFFF) * CC + cid8);
    P.q01 = *(const uint4*)(xb + (cA >> 16)    * CC + cid8);
    P.q10 = *(const uint4*)(xb + (cB & 0xFFFF) * CC + cid8);
    P.q11 = *(const uint4*)(xb + (cB >> 16)    * CC + cid8);
}

__device__ __forceinline__ void gather_commit(const Pref& P, __half* ss, int cid8) {
    __half2 w00v = __low2half2(P.wA), w01v = __high2half2(P.wA);
    __half2 w10v = __low2half2(P.wB), w11v = __high2half2(P.wB);
    const __half2* h00 = (const __half2*)&P.q00;
    const __half2* h01 = (const __half2*)&P.q01;
    const __half2* h10 = (const __half2*)&P.q10;
    const __half2* h11 = (const __half2*)&P.q11;
    uint4 r;
    __half2* ro = (__half2*)&r;
#pragma unroll
    for (int u = 0; u < 4; u++)
        ro[u] = __hfma2(h11[u], w11v,
                __hfma2(h10[u], w10v,
                __hfma2(h01[u], w01v,
                __hmul2(h00[u], w00v))));
    *(uint4*)&ss[P.pp * SSH + cid8] = r;
}

__device__ __forceinline__ void stage_w(__half* dst, int k, int tid) {
    const uint4* src = (const uint4*)(g_wth + k * CC * OO);
#pragma unroll
    for (int t = 0; t < 2; t++) {
        int idx = tid + t * 256;
        int j = idx >> 3, o8 = (idx & 7) * 8;
        *(uint4*)&dst[j * WSH + o8] = src[idx];
    }
}

__device__ __forceinline__ void mma_half(
    float (&acc)[2][4][4], const __half* ss, const __half* sw,
    int kkbase, int lane, int p0, int n0)
{
#pragma unroll
    for (int kk = kkbase; kk < kkbase + 2; kk++) {
        int j = kk * 16;
        uint32_t A[2][4], Bf[4][2];
#pragma unroll
        for (int mf = 0; mf < 2; mf++) {
            uint32_t addr = smem_u32(
                &ss[(p0 + mf * 16 + (lane & 15)) * SSH + j + ((lane >> 4) << 3)]);
            LDSM_X4(A[mf][0], A[mf][1], A[mf][2], A[mf][3], addr);
        }
#pragma unroll
        for (int q = 0; q < 2; q++) {
            uint32_t addr = smem_u32(
                &sw[(j + (lane & 8) + (lane & 7)) * WSH
                    + n0 + (q * 2 + (lane >> 4)) * 8]);
            LDSM_X4_T(Bf[2 * q][0], Bf[2 * q][1], Bf[2 * q + 1][0], Bf[2 * q + 1][1], addr);
        }
#pragma unroll
        for (int mf = 0; mf < 2; mf++)
#pragma unroll
            for (int nt = 0; nt < 4; nt++)
                MMA_F16(acc[mf][nt], A[mf], Bf[nt]);
    }
}

__global__ __launch_bounds__(256, 2) void k_deform(const float* __restrict__ bias,
                                                   float* __restrict__ out) {
    extern __shared__ __align__(16) char smraw[];
    __half*  s_wb = (__half*)smraw;                      // 2 x [64][WSH]   18432 B
    __half*  s_sb = (__half*)(smraw + 18432);            // 2 x [128][SSH]  36864 B
    int*     s_cA = (int*)(smraw + 55296);               // packed (c00|c01<<16)
    int*     s_cB = s_cA + KK * PIX;                     // packed (c10|c11<<16)
    __half2* s_wA = (__half2*)(s_cB + KK * PIX);         // (w00,w01)
    __half2* s_wB = s_wA + KK * PIX;                     // (w10,w11)
    float*   s_offrow = (float*)(smraw + 18432);         // phase-0 alias of sbuf0
    float*   s_out = (float*)smraw;                      // epilogue alias, 32768 B

    int tid  = threadIdx.x;
    int b    = blockIdx.y;
    int ho   = blockIdx.x;
    int lane = tid & 31;
    int wid  = tid >> 5;

    int g  = lane >> 2;
    int tg = lane & 3;
    int p0 = (wid >> 1) * 32;
    int n0 = (wid & 1) * 32;

    int ppi  = lane >> 3;        // pixel-in-group 0..3 (sampling)
    int cid8 = (lane & 7) * 8;   // channel base (8 ch, 16B)
    int pbase = wid * 4 + ppi;   // this thread's pixel within each 32-group

    const __half* xb = g_xth + (size_t)b * HWSZ * CC;

    // ---- phase 0: offsets row -> smem (coalesced), then all 9 taps' params ----
    {
        const float4* osrc = (const float4*)(g_off + (size_t)(b * HWSZ + ho * WW) * OOFF);
        for (int i = tid; i < PIX * OOFF / 4; i += 256)
            ((float4*)s_offrow)[i] = osrc[i];
    }
    __syncthreads();
    for (int i = tid; i < KK * PIX; i += 256) {
        int p = i & (PIX - 1);
        int k = i >> 7;
        float dy = s_offrow[p * OOFF + 2 * k];
        float dx = s_offrow[p * OOFF + 2 * k + 1];
        int ki = k / 3, kj = k % 3;
        float py = (float)(ho - 1 + ki) + dy;
        float px = (float)(p - 1 + kj) + dx;
        float fy = floorf(py), fx = floorf(px);
        float wy = py - fy, wx = px - fx;
        int iy = (int)fy, ix = (int)fx;
        float vy0 = (iy >= 0 && iy < HH) ? 1.f : 0.f;
        float vy1 = (iy + 1 >= 0 && iy + 1 < HH) ? 1.f : 0.f;
        float vx0 = (ix >= 0 && ix < WW) ? 1.f : 0.f;
        float vx1 = (ix + 1 >= 0 && ix + 1 < WW) ? 1.f : 0.f;
        float w00 = (1.f - wy) * (1.f - wx) * vy0 * vx0;
        float w01 = (1.f - wy) * wx         * vy0 * vx1;
        float w10 = wy         * (1.f - wx) * vy1 * vx0;
        float w11 = wy         * wx         * vy1 * vx1;
        int iy0 = min(max(iy, 0), HH - 1);
        int iy1 = min(max(iy + 1, 0), HH - 1);
        int ix0 = min(max(ix, 0), WW - 1);
        int ix1 = min(max(ix + 1, 0), WW - 1);
        s_cA[i] = (iy0 * WW + ix0) | ((iy0 * WW + ix1) << 16);
        s_cB[i] = (iy1 * WW + ix0) | ((iy1 * WW + ix1) << 16);
        s_wA[i] = __floats2half2_rn(w00, w01);
        s_wB[i] = __floats2half2_rn(w10, w11);
    }
    __syncthreads();   // params visible; s_offrow reads done before sbuf0 overwrite

    float acc[2][4][4];
#pragma unroll
    for (int mf = 0; mf < 2; mf++)
#pragma unroll
        for (int nt = 0; nt < 4; nt++)
#pragma unroll
            for (int c = 0; c < 4; c++) acc[mf][nt][c] = 0.f;

    // ---- prologue: tap 0 into buffer 0 ----
    stage_w(s_wb, 0, tid);
    {
        Pref P;
#pragma unroll
        for (int it = 0; it < 4; it++) {
            gather_issue(P, 0, it * 32 + pbase, xb, cid8, s_cA, s_cB, s_wA, s_wB);
            gather_commit(P, s_sb, cid8);
        }
    }
    __syncthreads();

    // ---- pipelined tap loop: one barrier per tap ----
#pragma unroll 1
    for (int k = 0; k < KK; k++) {
        int cur = k & 1, nxt = cur ^ 1;
        const __half* sw = s_wb + cur * WBUFH;
        const __half* ss = s_sb + cur * SBUFH;
        __half* ssn = s_sb + nxt * SBUFH;
        bool more = (k + 1 < KK);

        Pref P0, P1;
        if (more) {
            gather_issue(P0, k + 1, 0 * 32 + pbase, xb, cid8, s_cA, s_cB, s_wA, s_wB);
            gather_issue(P1, k + 1, 1 * 32 + pbase, xb, cid8, s_cA, s_cB, s_wA, s_wB);
        }
        mma_half(acc, ss, sw, 0, lane, p0, n0);   // LDGs in flight under MMA
        if (more) {
            gather_commit(P0, ssn, cid8);
            gather_commit(P1, ssn, cid8);
            gather_issue(P0, k + 1, 2 * 32 + pbase, xb, cid8, s_cA, s_cB, s_wA, s_wB);
            gather_issue(P1, k + 1, 3 * 32 + pbase, xb, cid8, s_cA, s_cB, s_wA, s_wB);
        }
        mma_half(acc, ss, sw, 2, lane, p0, n0);
        if (more) {
            gather_commit(P0, ssn, cid8);
            gather_commit(P1, ssn, cid8);
            stage_w(s_wb + nxt * WBUFH, k + 1, tid);
        }
        __syncthreads();
    }

    // ---- epilogue: stage output as [o][p] for coalesced NCHW stores ----
#pragma unroll
    for (int mf = 0; mf < 2; mf++)
#pragma unroll
        for (int nt = 0; nt < 4; nt++) {
            int row = p0 + mf * 16 + g;
            int col = n0 + nt * 8 + 2 * tg;
            s_out[col * PIX + row]           = acc[mf][nt][0];
            s_out[(col + 1) * PIX + row]     = acc[mf][nt][1];
            s_out[col * PIX + row + 8]       = acc[mf][nt][2];
            s_out[(col + 1) * PIX + row + 8] = acc[mf][nt][3];
        }
    __syncthreads();

    float* ob = out + (size_t)(b * OO) * HWSZ + ho * WW;
    for (int i = tid; i < OO * PIX / 4; i += 256) {
        int o = i >> 5, p4 = i & 31;
        float4 v = ((const float4*)s_out)[i];
        float bo = bias[o];
        v.x += bo; v.y += bo; v.z += bo; v.w += bo;
        ((float4*)(ob + (size_t)o * HWSZ))[p4] = v;
    }
}

// ---------------- launch ----------------
#define DEFORM_SMEM (18432 + 36864 + 2 * KK * PIX * 4 + 2 * KK * PIX * 4)  // 73728
#define OFFC_SMEM   (31104 + 35360 + 9216)                                 // 75680

extern "C" void kernel_launch(void* const* d_in, const int* in_sizes, int n_in,
                              void* d_out, int out_size) {
    const float* x     = (const float*)d_in[0];
    const float* w_off = (const float*)d_in[1];
    const float* b_off = (const float*)d_in[2];
    const float* w     = (const float*)d_in[3];
    const float* bias  = (const float*)d_in[4];
    float* out = (float*)d_out;

    (void)in_sizes; (void)n_in; (void)out_size;

    cudaFuncSetAttribute(k_offconv, cudaFuncAttributeMaxDynamicSharedMemorySize, OFFC_SMEM);
    cudaFuncSetAttribute(k_deform,  cudaFuncAttributeMaxDynamicSharedMemorySize, DEFORM_SMEM);

    dim3 tpb(32, 8);
    k_transpose<<<dim3(HWSZ / 32, CC / 64, BB), tpb>>>(x);
    k_wprep<<<(KK * CC * OO + 255) / 256, 256>>>(w, w_off);
    k_offconv<<<dim3(HH, BB), 256, OFFC_SMEM>>>(b_off);
    k_deform<<<dim3(HH, BB), 256, DEFORM_SMEM>>>(bias, out);
}

// round 12
// speedup vs baseline: 4.6283x; 1.0011x over previous
#include <cuda_runtime.h>
#include <cuda_fp16.h>
#include <cstdint>

#define BB   8
#define CC   64
#define HH   128
#define WW   128
#define OO   64
#define OOFF 18
#define KK   9
#define HWSZ (HH*WW)

#define PIX  128   // pixels per block in k_deform (one full row)
#define SSH  72    // s_samp pixel stride (halves) -> 144B rows, conflict-free ldmatrix
#define WSH  72    // s_w k-row stride (halves)
#define WBUFH (CC*WSH)    // 4608 halves per weight buffer
#define SBUFH (PIX*SSH)   // 9216 halves per sample buffer

#define NOFF 24    // offset-conv N padded to 24 (3 x n8 tiles)
#define XSTR 136   // offset-conv staged-row stride (halves)
#define WOSTR 72   // offset-conv weight k-stride (halves), layout [tap][n][k]

// ---------------- scratch (no allocations allowed) ----------------
__device__ __align__(16) __half g_xth[BB*HWSZ*CC];      // x in NHWC, fp16
__device__ __align__(16) float  g_off[BB*HWSZ*OOFF];    // offsets NHWC fp32
__device__ __align__(16) __half g_wth[KK*CC*OO];        // main weights [k][c][o] fp16
__device__ __align__(16) __half g_wtoffh[KK*NOFF*CC];   // offset weights [k][n][c] fp16, zero-pad

__device__ __forceinline__ uint32_t smem_u32(const void* p) {
    return (uint32_t)__cvta_generic_to_shared(p);
}

#define MMA_F16(d, a, b)                                                      \
    asm volatile("mma.sync.aligned.m16n8k16.row.col.f32.f16.f16.f32 "         \
                 "{%0,%1,%2,%3}, {%4,%5,%6,%7}, {%8,%9}, {%0,%1,%2,%3};"      \
                 : "+f"(d[0]), "+f"(d[1]), "+f"(d[2]), "+f"(d[3])             \
                 : "r"(a[0]), "r"(a[1]), "r"(a[2]), "r"(a[3]),                \
                   "r"(b[0]), "r"(b[1]))

#define LDSM_X4(r0, r1, r2, r3, addr)                                         \
    asm volatile("ldmatrix.sync.aligned.m8n8.x4.shared.b16 {%0,%1,%2,%3}, [%4];" \
                 : "=r"(r0), "=r"(r1), "=r"(r2), "=r"(r3) : "r"(addr))

#define LDSM_X4_T(r0, r1, r2, r3, addr)                                       \
    asm volatile("ldmatrix.sync.aligned.m8n8.x4.trans.shared.b16 {%0,%1,%2,%3}, [%4];" \
                 : "=r"(r0), "=r"(r1), "=r"(r2), "=r"(r3) : "r"(addr))

// ---------------- kernel 1: NCHW fp32 -> NHWC fp16 ----------------
__global__ void k_transpose(const float* __restrict__ x) {
    __shared__ float tile[64][33];
    int b   = blockIdx.z;
    int hw0 = blockIdx.x * 32;
    int c0  = blockIdx.y * 64;
    int tx = threadIdx.x, ty = threadIdx.y;
    const float* xp = x + (size_t)b * CC * HWSZ;
#pragma unroll
    for (int i = 0; i < 64; i += 8)
        tile[ty + i][tx] = xp[(size_t)(c0 + ty + i) * HWSZ + hw0 + tx];
    __syncthreads();
    __half2* op = (__half2*)(g_xth + (size_t)b * HWSZ * CC);
#pragma unroll
    for (int i = 0; i < 32; i += 8) {
        int row = ty + i;
        float lo = tile[2 * tx][row], hi = tile[2 * tx + 1][row];
        op[((size_t)(hw0 + row) * CC + c0) / 2 + tx] = __floats2half2_rn(lo, hi);
    }
}

// ---------------- kernel 2: weight prep ----------------
__global__ void k_wprep(const float* __restrict__ w, const float* __restrict__ woff) {
    int i = blockIdx.x * 256 + threadIdx.x;
    if (i < KK * CC * OO) {
        int k = i / (CC * OO);
        int r = i % (CC * OO);
        int c = r / OO;
        int o = r % OO;
        g_wth[i] = __float2half_rn(w[(o * CC + c) * KK + k]);
    }
    if (i < KK * NOFF * CC) {
        int t = i / (NOFF * CC);
        int r = i % (NOFF * CC);
        int n = r / CC;
        int c = r % CC;
        g_wtoffh[i] = (n < OOFF)
            ? __float2half_rn(woff[(n * CC + c) * KK + t])
            : __float2half_rn(0.f);
    }
}

// ---------------- kernel 3: offset conv via fp16 MMA ----------------
// Block = one output row. Stage 3 input rows (fp16, raw copy, zero-pad cols);
// 9 taps = shifted-A GEMMs, K=64 (4 k16 chunks), N=24 (18 used).
__global__ __launch_bounds__(256) void k_offconv(const float* __restrict__ boff) {
    extern __shared__ __align__(16) char smo[];
    __half* s_wo  = (__half*)smo;                        // [9][24][WOSTR] 31104 B
    __half* s_xr  = (__half*)(smo + 31104);              // [130][XSTR]    35360 B
    float*  s_off = (float*)(smo + 31104 + 35360);       // [128*18]        9216 B

    int tid  = threadIdx.x;
    int b    = blockIdx.y;
    int ho   = blockIdx.x;
    int lane = tid & 31;
    int wid  = tid >> 5;
    int g  = lane >> 2;
    int tg = lane & 3;
    int p0 = wid * 16;

    // stage all 9 taps' weights [t][n][k] with stride WOSTR
    {
        const uint4* src = (const uint4*)g_wtoffh;
        for (int i = tid; i < KK * NOFF * CC / 8; i += 256) {
            int tn = i >> 3, c8 = (i & 7) * 8;           // tn = t*24 + n
            *(uint4*)&s_wo[tn * WOSTR + c8] = src[i];
        }
    }

    float acc[3][4];
#pragma unroll
    for (int nt = 0; nt < 3; nt++)
#pragma unroll
        for (int c = 0; c < 4; c++) acc[nt][c] = 0.f;

#pragma unroll 1
    for (int ki = 0; ki < 3; ki++) {
        __syncthreads();
        int y = ho - 1 + ki;
        if (y >= 0 && y < HH) {
            const uint4* src = (const uint4*)(g_xth + (size_t)(b * HWSZ + y * WW) * CC);
#pragma unroll
            for (int t = 0; t < 4; t++) {
                int idx = tid + t * 256;                 // 1024 uint4 = 128 rows x 8
                int p = idx >> 3, c8 = (idx & 7) * 8;
                *(uint4*)&s_xr[(p + 1) * XSTR + c8] = src[idx];
            }
            if (tid < 16) {   // zero pad rows 0 and 129 (first 64 ch)
                int row = (tid >> 3) ? 129 : 0;
                int c8 = (tid & 7) * 8;
                *(uint4*)&s_xr[row * XSTR + c8] = make_uint4(0, 0, 0, 0);
            }
        } else {
            uint4 z = make_uint4(0, 0, 0, 0);
            for (int i = tid; i < 130 * XSTR / 8; i += 256)
                ((uint4*)s_xr)[i] = z;
        }
        __syncthreads();

#pragma unroll
        for (int kj = 0; kj < 3; kj++) {
            const __half* wt = &s_wo[(ki * 3 + kj) * NOFF * WOSTR];
            int rbase = (p0 + g + kj) * XSTR;
#pragma unroll
            for (int kk = 0; kk < 4; kk++) {
                int j = kk * 16;
                uint32_t a[4], bf[3][2];
                a[0] = *(const uint32_t*)&s_xr[rbase + j + 2 * tg];
                a[1] = *(const uint32_t*)&s_xr[rbase + 8 * XSTR + j + 2 * tg];
                a[2] = *(const uint32_t*)&s_xr[rbase + j + 2 * tg + 8];
                a[3] = *(const uint32_t*)&s_xr[rbase + 8 * XSTR + j + 2 * tg + 8];
#pragma unroll
                for (int nt = 0; nt < 3; nt++) {
                    int n = nt * 8 + g;
                    bf[nt][0] = *(const uint32_t*)&wt[n * WOSTR + j + 2 * tg];
                    bf[nt][1] = *(const uint32_t*)&wt[n * WOSTR + j + 2 * tg + 8];
                }
#pragma unroll
                for (int nt = 0; nt < 3; nt++)
                    MMA_F16(acc[nt], a, bf[nt]);
            }
        }
    }

    __syncthreads();
#pragma unroll
    for (int nt = 0; nt < 3; nt++) {
        int col = nt * 8 + 2 * tg;
        if (col < OOFF) {
            s_off[(p0 + g) * OOFF + col]         = acc[nt][0];
            s_off[(p0 + g) * OOFF + col + 1]     = acc[nt][1];
            s_off[(p0 + g + 8) * OOFF + col]     = acc[nt][2];
            s_off[(p0 + g + 8) * OOFF + col + 1] = acc[nt][3];
        }
    }
    __syncthreads();

    float* op = g_off + (size_t)(b * HWSZ + ho * WW) * OOFF;
    for (int i = tid; i < PIX * OOFF; i += 256)
        op[i] = s_off[i] + boff[i % OOFF];
}

// ---------------- kernel 4: deformable conv, pipelined fp16 MMA ----------------
struct Pref {
    uint4 q00, q01, q10, q11;
    __half2 wA, wB;
    int pp;
};

__device__ __forceinline__ void gather_issue(
    Pref& P, int kidx, int pp, const __half* __restrict__ xb, int cid8,
    const int* s_cA, const int* s_cB, const __half2* s_wA, const __half2* s_wB)
{
    int idx = kidx * PIX + pp;
    int cA = s_cA[idx], cB = s_cB[idx];
    P.wA = s_wA[idx];
    P.wB = s_wB[idx];
    P.pp = pp;
    P.q00 = *(const uint4*)(xb + (cA & 0xFFFF) * CC + cid8);
    P.q01 = *(const uint4*)(xb + (cA >> 16)    * CC + cid8);
    P.q10 = *(const uint4*)(xb + (cB & 0xFFFF) * CC + cid8);
    P.q11 = *(const uint4*)(xb + (cB >> 16)    * CC + cid8);
}

__device__ __forceinline__ void gather_commit(const Pref& P, __half* ss, int cid8) {
    __half2 w00v = __low2half2(P.wA), w01v = __high2half2(P.wA);
    __half2 w10v = __low2half2(P.wB), w11v = __high2half2(P.wB);
    const __half2* h00 = (const __half2*)&P.q00;
    const __half2* h01 = (const __half2*)&P.q01;
    const __half2* h10 = (const __half2*)&P.q10;
    const __half2* h11 = (const __half2*)&P.q11;
    uint4 r;
    __half2* ro = (__half2*)&r;
#pragma unroll
    for (int u = 0; u < 4; u++)
        ro[u] = __hfma2(h11[u], w11v,
                __hfma2(h10[u], w10v,
                __hfma2(h01[u], w01v,
                __hmul2(h00[u], w00v))));
    *(uint4*)&ss[P.pp * SSH + cid8] = r;
}

__device__ __forceinline__ void stage_w(__half* dst, int k, int tid) {
    const uint4* src = (const uint4*)(g_wth + k * CC * OO);
#pragma unroll
    for (int t = 0; t < 2; t++) {
        int idx = tid + t * 256;
        int j = idx >> 3, o8 = (idx & 7) * 8;
        *(uint4*)&dst[j * WSH + o8] = src[idx];
    }
}

__device__ __forceinline__ void mma_half(
    float (&acc)[2][4][4], const __half* ss, const __half* sw,
    int kkbase, int lane, int p0, int n0)
{
#pragma unroll
    for (int kk = kkbase; kk < kkbase + 2; kk++) {
        int j = kk * 16;
        uint32_t A[2][4], Bf[4][2];
#pragma unroll
        for (int mf = 0; mf < 2; mf++) {
            uint32_t addr = smem_u32(
                &ss[(p0 + mf * 16 + (lane & 15)) * SSH + j + ((lane >> 4) << 3)]);
            LDSM_X4(A[mf][0], A[mf][1], A[mf][2], A[mf][3], addr);
        }
#pragma unroll
        for (int q = 0; q < 2; q++) {
            uint32_t addr = smem_u32(
                &sw[(j + (lane & 8) + (lane & 7)) * WSH
                    + n0 + (q * 2 + (lane >> 4)) * 8]);
            LDSM_X4_T(Bf[2 * q][0], Bf[2 * q][1], Bf[2 * q + 1][0], Bf[2 * q + 1][1], addr);
        }
#pragma unroll
        for (int mf = 0; mf < 2; mf++)
#pragma unroll
            for (int nt = 0; nt < 4; nt++)
                MMA_F16(acc[mf][nt], A[mf], Bf[nt]);
    }
}

__global__ __launch_bounds__(256, 2) void k_deform(const float* __restrict__ bias,
                                                   float* __restrict__ out) {
    extern __shared__ __align__(16) char smraw[];
    __half*  s_wb = (__half*)smraw;                      // 2 x [64][WSH]   18432 B
    __half*  s_sb = (__half*)(smraw + 18432);            // 2 x [128][SSH]  36864 B
    int*     s_cA = (int*)(smraw + 55296);               // packed (c00|c01<<16)
    int*     s_cB = s_cA + KK * PIX;                     // packed (c10|c11<<16)
    __half2* s_wA = (__half2*)(s_cB + KK * PIX);         // (w00,w01)
    __half2* s_wB = s_wA + KK * PIX;                     // (w10,w11)
    float*   s_offrow = (float*)(smraw + 18432);         // phase-0 alias of sbuf0
    float*   s_out = (float*)smraw;                      // epilogue alias, 32768 B

    int tid  = threadIdx.x;
    int b    = blockIdx.y;
    int ho   = blockIdx.x;
    int lane = tid & 31;
    int wid  = tid >> 5;

    int g  = lane >> 2;
    int tg = lane & 3;
    int p0 = (wid >> 1) * 32;
    int n0 = (wid & 1) * 32;

    int ppi  = lane >> 3;        // pixel-in-group 0..3 (sampling)
    int cid8 = (lane & 7) * 8;   // channel base (8 ch, 16B)
    int pbase = wid * 4 + ppi;   // this thread's pixel within each 32-group

    const __half* xb = g_xth + (size_t)b * HWSZ * CC;

    // ---- phase 0: offsets row -> smem (coalesced), then all 9 taps' params ----
    {
        const float4* osrc = (const float4*)(g_off + (size_t)(b * HWSZ + ho * WW) * OOFF);
        for (int i = tid; i < PIX * OOFF / 4; i += 256)
            ((float4*)s_offrow)[i] = osrc[i];
    }
    __syncthreads();
    for (int i = tid; i < KK * PIX; i += 256) {
        int p = i & (PIX - 1);
        int k = i >> 7;
        float dy = s_offrow[p * OOFF + 2 * k];
        float dx = s_offrow[p * OOFF + 2 * k + 1];
        int ki = k / 3, kj = k % 3;
        float py = (float)(ho - 1 + ki) + dy;
        float px = (float)(p - 1 + kj) + dx;
        float fy = floorf(py), fx = floorf(px);
        float wy = py - fy, wx = px - fx;
        int iy = (int)fy, ix = (int)fx;
        float vy0 = (iy >= 0 && iy < HH) ? 1.f : 0.f;
        float vy1 = (iy + 1 >= 0 && iy + 1 < HH) ? 1.f : 0.f;
        float vx0 = (ix >= 0 && ix < WW) ? 1.f : 0.f;
        float vx1 = (ix + 1 >= 0 && ix + 1 < WW) ? 1.f : 0.f;
        float w00 = (1.f - wy) * (1.f - wx) * vy0 * vx0;
        float w01 = (1.f - wy) * wx         * vy0 * vx1;
        float w10 = wy         * (1.f - wx) * vy1 * vx0;
        float w11 = wy         * wx         * vy1 * vx1;
        int iy0 = min(max(iy, 0), HH - 1);
        int iy1 = min(max(iy + 1, 0), HH - 1);
        int ix0 = min(max(ix, 0), WW - 1);
        int ix1 = min(max(ix + 1, 0), WW - 1);
        s_cA[i] = (iy0 * WW + ix0) | ((iy0 * WW + ix1) << 16);
        s_cB[i] = (iy1 * WW + ix0) | ((iy1 * WW + ix1) << 16);
        s_wA[i] = __floats2half2_rn(w00, w01);
        s_wB[i] = __floats2half2_rn(w10, w11);
    }
    __syncthreads();   // params visible; s_offrow reads done before sbuf0 overwrite

    float acc[2][4][4];
#pragma unroll
    for (int mf = 0; mf < 2; mf++)
#pragma unroll
        for (int nt = 0; nt < 4; nt++)
#pragma unroll
            for (int c = 0; c < 4; c++) acc[mf][nt][c] = 0.f;

    // ---- prologue: tap 0 into buffer 0 ----
    stage_w(s_wb, 0, tid);
    {
        Pref P;
#pragma unroll
        for (int it = 0; it < 4; it++) {
            gather_issue(P, 0, it * 32 + pbase, xb, cid8, s_cA, s_cB, s_wA, s_wB);
            gather_commit(P, s_sb, cid8);
        }
    }
    __syncthreads();

    // ---- pipelined tap loop: one barrier per tap ----
#pragma unroll 1
    for (int k = 0; k < KK; k++) {
        int cur = k & 1, nxt = cur ^ 1;
        const __half* sw = s_wb + cur * WBUFH;
        const __half* ss = s_sb + cur * SBUFH;
        __half* ssn = s_sb + nxt * SBUFH;
        bool more = (k + 1 < KK);

        Pref P0, P1;
        if (more) {
            gather_issue(P0, k + 1, 0 * 32 + pbase, xb, cid8, s_cA, s_cB, s_wA, s_wB);
            gather_issue(P1, k + 1, 1 * 32 + pbase, xb, cid8, s_cA, s_cB, s_wA, s_wB);
        }
        mma_half(acc, ss, sw, 0, lane, p0, n0);   // LDGs in flight under MMA
        if (more) {
            gather_commit(P0, ssn, cid8);
            gather_commit(P1, ssn, cid8);
            gather_issue(P0, k + 1, 2 * 32 + pbase, xb, cid8, s_cA, s_cB, s_wA, s_wB);
            gather_issue(P1, k + 1, 3 * 32 + pbase, xb, cid8, s_cA, s_cB, s_wA, s_wB);
        }
        mma_half(acc, ss, sw, 2, lane, p0, n0);
        if (more) {
            gather_commit(P0, ssn, cid8);
            gather_commit(P1, ssn, cid8);
            stage_w(s_wb + nxt * WBUFH, k + 1, tid);
        }
        __syncthreads();
    }

    // ---- epilogue: stage output as [o][p] for coalesced NCHW stores ----
#pragma unroll
    for (int mf = 0; mf < 2; mf++)
#pragma unroll
        for (int nt = 0; nt < 4; nt++) {
            int row = p0 + mf * 16 + g;
            int col = n0 + nt * 8 + 2 * tg;
            s_out[col * PIX + row]           = acc[mf][nt][0];
            s_out[(col + 1) * PIX + row]     = acc[mf][nt][1];
            s_out[col * PIX + row + 8]       = acc[mf][nt][2];
            s_out[(col + 1) * PIX + row + 8] = acc[mf][nt][3];
        }
    __syncthreads();

    float* ob = out + (size_t)(b * OO) * HWSZ + ho * WW;
    for (int i = tid; i < OO * PIX / 4; i += 256) {
        int o = i >> 5, p4 = i & 31;
        float4 v = ((const float4*)s_out)[i];
        float bo = bias[o];
        v.x += bo; v.y += bo; v.z += bo; v.w += bo;
        ((float4*)(ob + (size_t)o * HWSZ))[p4] = v;
    }
}

// ---------------- launch ----------------
#define DEFORM_SMEM (18432 + 36864 + 2 * KK * PIX * 4 + 2 * KK * PIX * 4)  // 73728
#define OFFC_SMEM   (31104 + 35360 + 9216)                                 // 75680

extern "C" void kernel_launch(void* const* d_in, const int* in_sizes, int n_in,
                              void* d_out, int out_size) {
    const float* x     = (const float*)d_in[0];
    const float* w_off = (const float*)d_in[1];
    const float* b_off = (const float*)d_in[2];
    const float* w     = (const float*)d_in[3];
    const float* bias  = (const float*)d_in[4];
    float* out = (float*)d_out;

    (void)in_sizes; (void)n_in; (void)out_size;

    cudaFuncSetAttribute(k_offconv, cudaFuncAttributeMaxDynamicSharedMemorySize, OFFC_SMEM);
    cudaFuncSetAttribute(k_deform,  cudaFuncAttributeMaxDynamicSharedMemorySize, DEFORM_SMEM);

    dim3 tpb(32, 8);
    k_transpose<<<dim3(HWSZ / 32, CC / 64, BB), tpb>>>(x);
    k_wprep<<<(KK * CC * OO + 255) / 256, 256>>>(w, w_off);
    k_offconv<<<dim3(HH, BB), 256, OFFC_SMEM>>>(b_off);
    k_deform<<<dim3(HH, BB), 256, DEFORM_SMEM>>>(bias, out);
}